// round 5
// baseline (speedup 1.0000x reference)
#include <cuda_runtime.h>
#include <cuda_bf16.h>
#include <math.h>

// Problem constants
#define B_   2
#define QL_  2048
#define HID_ 2048
#define NH_  32
#define KVH_ 8
#define D_   64

// Scratch (device globals — no allocation allowed)
__device__ float g_Q[(size_t)B_ * NH_  * QL_ * D_];   // [b,h,q,d]
__device__ float g_K[(size_t)B_ * KVH_ * QL_ * D_];
__device__ float g_V[(size_t)B_ * KVH_ * QL_ * D_];
__device__ float g_A[(size_t)B_ * QL_ * HID_];        // attn out, [b*q, h*d] row-major
__device__ float g_cos[QL_ * 32];                     // RoPE tables [t][j]
__device__ float g_sin[QL_ * 32];

// ---------------------------------------------------------------------------
// SGEMM: C[M,N] = A[M,K] @ B[K,N].  BM=BN=128, BK=16, 256 thr, 8x8 per thread.
// Register-prefetch double buffering: tile k+1 GMEM loads issue before the
// FFMA loop of tile k.
// MODE 0: plain row-major C.
// MODE 1: permuted write: row r=(b*QL+t), col c=(h*64+dd) ->
//         C[((b*H+h)*QL + t)*64 + dd]   (head-major layout for attention)
// ---------------------------------------------------------------------------
template<int MODE>
__global__ void __launch_bounds__(256)
sgemm_kernel(const float* __restrict__ A, const float* __restrict__ B,
             float* __restrict__ C, int M, int N, int K, int H, int QL)
{
    __shared__ __align__(16) float As[16][132];
    __shared__ __align__(16) float Bs[16][132];

    const int tid = threadIdx.x;
    const int tx  = tid & 15;
    const int ty  = tid >> 4;
    const int bx  = blockIdx.x;
    const int by  = blockIdx.y;

    const float* Ab = A + (size_t)by * 128 * K;
    const float* Bb = B + (size_t)bx * 128;

    // per-thread load coordinates (invariant across k tiles)
    const int ar0 = (tid)       >> 2, a40 = (tid)       & 3;
    const int ar1 = (tid + 256) >> 2, a41 = (tid + 256) & 3;
    const int br0 = (tid)       >> 5, b40 = (tid)       & 31;
    const int br1 = (tid + 256) >> 5, b41 = (tid + 256) & 31;

    float acc[8][8];
#pragma unroll
    for (int i = 0; i < 8; i++)
#pragma unroll
        for (int j = 0; j < 8; j++) acc[i][j] = 0.f;

    // prefetch tile 0 into registers
    float4 pA0 = *(const float4*)(Ab + (size_t)ar0 * K + a40 * 4);
    float4 pA1 = *(const float4*)(Ab + (size_t)ar1 * K + a41 * 4);
    float4 pB0 = *(const float4*)(Bb + (size_t)br0 * N + b40 * 4);
    float4 pB1 = *(const float4*)(Bb + (size_t)br1 * N + b41 * 4);

    for (int k0 = 0; k0 < K; k0 += 16) {
        // store prefetched tile to SMEM (A transposed)
        As[a40 * 4 + 0][ar0] = pA0.x;
        As[a40 * 4 + 1][ar0] = pA0.y;
        As[a40 * 4 + 2][ar0] = pA0.z;
        As[a40 * 4 + 3][ar0] = pA0.w;
        As[a41 * 4 + 0][ar1] = pA1.x;
        As[a41 * 4 + 1][ar1] = pA1.y;
        As[a41 * 4 + 2][ar1] = pA1.z;
        As[a41 * 4 + 3][ar1] = pA1.w;
        *(float4*)&Bs[br0][b40 * 4] = pB0;
        *(float4*)&Bs[br1][b41 * 4] = pB1;
        __syncthreads();

        // prefetch next tile (overlaps with FFMA loop below)
        if (k0 + 16 < K) {
            pA0 = *(const float4*)(Ab + (size_t)ar0 * K + k0 + 16 + a40 * 4);
            pA1 = *(const float4*)(Ab + (size_t)ar1 * K + k0 + 16 + a41 * 4);
            pB0 = *(const float4*)(Bb + (size_t)(k0 + 16 + br0) * N + b40 * 4);
            pB1 = *(const float4*)(Bb + (size_t)(k0 + 16 + br1) * N + b41 * 4);
        }

#pragma unroll
        for (int k = 0; k < 16; k++) {
            float4 a0 = *(float4*)&As[k][ty * 4];
            float4 a1 = *(float4*)&As[k][ty * 4 + 64];
            float4 b0 = *(float4*)&Bs[k][tx * 4];
            float4 b1 = *(float4*)&Bs[k][tx * 4 + 64];
            float av[8] = {a0.x, a0.y, a0.z, a0.w, a1.x, a1.y, a1.z, a1.w};
            float bv[8] = {b0.x, b0.y, b0.z, b0.w, b1.x, b1.y, b1.z, b1.w};
#pragma unroll
            for (int i = 0; i < 8; i++)
#pragma unroll
                for (int j = 0; j < 8; j++)
                    acc[i][j] += av[i] * bv[j];
        }
        __syncthreads();
    }

    // epilogue
#pragma unroll
    for (int ih = 0; ih < 2; ih++)
#pragma unroll
        for (int i = 0; i < 4; i++) {
            int gr = by * 128 + ty * 4 + i + ih * 64;
#pragma unroll
            for (int jh = 0; jh < 2; jh++) {
                int gc = bx * 128 + tx * 4 + jh * 64;
                float4 v = make_float4(acc[ih * 4 + i][jh * 4 + 0],
                                       acc[ih * 4 + i][jh * 4 + 1],
                                       acc[ih * 4 + i][jh * 4 + 2],
                                       acc[ih * 4 + i][jh * 4 + 3]);
                if (MODE == 0) {
                    *(float4*)&C[(size_t)gr * N + gc] = v;
                } else {
                    int b = gr / QL, t = gr % QL;
                    int h = gc >> 6, dd = gc & 63;
                    size_t o = (((size_t)b * H + h) * QL + t) * (size_t)64 + dd;
                    *(float4*)&C[o] = v;
                }
            }
        }
}

// ---------------------------------------------------------------------------
// RoPE cos/sin table: one entry per (t, j), computed ONCE in fp64.
// --use_fast_math breaks sincosf for args ~2000 rad; fp64 sincos of the
// reference's fp32 angle matches jnp to ~1e-7. Only 65536 entries -> ~10us.
// ---------------------------------------------------------------------------
__global__ void rope_table_kernel(float* __restrict__ ct, float* __restrict__ st,
                                  int Q)
{
    int idx = blockIdx.x * blockDim.x + threadIdx.x;
    if (idx >= Q * 32) return;
    int j = idx & 31;
    int t = idx >> 5;
    float freq = (float)(1.0 / pow(10000.0, (double)(2 * j) / 64.0));
    float ang  = (float)t * freq;      // fp32 rounding, same as reference
    double cd, sd;
    sincos((double)ang, &sd, &cd);
    ct[idx] = (float)cd;
    st[idx] = (float)sd;
}

// RoPE apply, in-place on [B, H, Q, 64]: memory-bound table lookup.
__global__ void rope_apply_kernel(float* __restrict__ buf,
                                  const float* __restrict__ ct,
                                  const float* __restrict__ st,
                                  int Q, int total)
{
    int idx = blockIdx.x * blockDim.x + threadIdx.x;
    if (idx >= total) return;
    int j  = idx & 31;
    int t  = (idx >> 5) % Q;
    int bh = idx / (32 * Q);
    size_t base = ((size_t)bh * Q + t) * 64;

    float c = ct[(t << 5) + j];
    float s = st[(t << 5) + j];

    float x1 = buf[base + j];
    float x2 = buf[base + j + 32];
    buf[base + j]      = x1 * c - x2 * s;
    buf[base + j + 32] = x2 * c + x1 * s;
}

// ---------------------------------------------------------------------------
// Causal flash attention with GQA.
// Grid: (Q/128, NH, B). 256 threads. BQ=128, BK=64, D=64.
// ---------------------------------------------------------------------------
#define QT_ST 132
#define KV_ST 68
#define ATTN_SMEM_FLOATS (64 * QT_ST + 64 * KV_ST + 64 * KV_ST + 128 * KV_ST)
#define ATTN_SMEM_BYTES  (ATTN_SMEM_FLOATS * 4)

__global__ void __launch_bounds__(256)
attn_kernel(const float* __restrict__ Qb, const float* __restrict__ Kb,
            const float* __restrict__ Vb, float* __restrict__ Ob,
            int Q, int H, int KVH)
{
    extern __shared__ float sm[];
    float* Qt = sm;                        // [64][QT_ST]
    float* Kt = Qt + 64 * QT_ST;           // [64][KV_ST]
    float* Vs = Kt + 64 * KV_ST;           // [64][KV_ST]
    float* Ps = Vs + 64 * KV_ST;           // [128][KV_ST]

    const int tid = threadIdx.x;
    const int tx  = tid & 15;
    const int ty  = tid >> 4;
    const int qt  = blockIdx.x;
    const int h   = blockIdx.y;
    const int b   = blockIdx.z;
    const int kvh = h / (H / KVH);
    const int q0  = qt * 128;

    const float* Qg = Qb + (((size_t)b * H + h) * Q + q0) * 64;
    const float* Kg = Kb + (((size_t)b * KVH + kvh) * Q) * 64;
    const float* Vg = Vb + (((size_t)b * KVH + kvh) * Q) * 64;

    // load Q tile (128x64) -> Qt[d][r]
#pragma unroll
    for (int it = 0; it < 8; it++) {
        int f  = tid + it * 256;   // 0..2047 float4s
        int r  = f >> 4;
        int d4 = f & 15;
        float4 v = *(const float4*)(Qg + (size_t)r * 64 + d4 * 4);
        Qt[(d4 * 4 + 0) * QT_ST + r] = v.x;
        Qt[(d4 * 4 + 1) * QT_ST + r] = v.y;
        Qt[(d4 * 4 + 2) * QT_ST + r] = v.z;
        Qt[(d4 * 4 + 3) * QT_ST + r] = v.w;
    }

    float m[8], l[8], acc[8][4];
#pragma unroll
    for (int i = 0; i < 8; i++) {
        m[i] = -1e30f;
        l[i] = 0.f;
#pragma unroll
        for (int j = 0; j < 4; j++) acc[i][j] = 0.f;
    }

    const int ktiles = (q0 + 128) / 64;   // causal: only tiles up to the diagonal
    const float scale = 0.125f;           // 1/sqrt(64)

    for (int kt = 0; kt < ktiles; kt++) {
        const int k0 = kt * 64;
        __syncthreads();   // previous iteration's readers done (also after Q load)

        // load K tile (64x64) -> Kt[d][c] ; V tile (64x64) -> Vs[c][d]
#pragma unroll
        for (int it = 0; it < 4; it++) {
            int f  = tid + it * 256;   // 0..1023 float4s
            int c  = f >> 4;
            int d4 = f & 15;
            float4 kv = *(const float4*)(Kg + (size_t)(k0 + c) * 64 + d4 * 4);
            Kt[(d4 * 4 + 0) * KV_ST + c] = kv.x;
            Kt[(d4 * 4 + 1) * KV_ST + c] = kv.y;
            Kt[(d4 * 4 + 2) * KV_ST + c] = kv.z;
            Kt[(d4 * 4 + 3) * KV_ST + c] = kv.w;
            float4 vv = *(const float4*)(Vg + (size_t)(k0 + c) * 64 + d4 * 4);
            *(float4*)&Vs[c * KV_ST + d4 * 4] = vv;
        }
        __syncthreads();

        // S = Q K^T  (8 rows x 4 cols per thread)
        float s[8][4];
#pragma unroll
        for (int i = 0; i < 8; i++)
#pragma unroll
            for (int j = 0; j < 4; j++) s[i][j] = 0.f;

#pragma unroll 4
        for (int d = 0; d < 64; d++) {
            float4 q0v = *(float4*)&Qt[d * QT_ST + ty * 8];
            float4 q1v = *(float4*)&Qt[d * QT_ST + ty * 8 + 4];
            float4 kv  = *(float4*)&Kt[d * KV_ST + tx * 4];
            float qv[8] = {q0v.x, q0v.y, q0v.z, q0v.w, q1v.x, q1v.y, q1v.z, q1v.w};
            float kvv[4] = {kv.x, kv.y, kv.z, kv.w};
#pragma unroll
            for (int i = 0; i < 8; i++)
#pragma unroll
                for (int j = 0; j < 4; j++)
                    s[i][j] += qv[i] * kvv[j];
        }

        // scale + causal mask + online softmax
#pragma unroll
        for (int i = 0; i < 8; i++) {
            int qg = q0 + ty * 8 + i;
            float rm = -1e30f;
#pragma unroll
            for (int j = 0; j < 4; j++) {
                int kg = k0 + tx * 4 + j;
                float v = s[i][j] * scale;
                if (kg > qg) v = -1e30f;
                s[i][j] = v;
                rm = fmaxf(rm, v);
            }
#pragma unroll
            for (int off = 8; off; off >>= 1)
                rm = fmaxf(rm, __shfl_xor_sync(0xffffffffu, rm, off));

            float newm = fmaxf(m[i], rm);
            float corr = __expf(m[i] - newm);
            float rsum = 0.f;
#pragma unroll
            for (int j = 0; j < 4; j++) {
                float p = __expf(s[i][j] - newm);
                s[i][j] = p;
                rsum += p;
            }
#pragma unroll
            for (int off = 8; off; off >>= 1)
                rsum += __shfl_xor_sync(0xffffffffu, rsum, off);

            l[i] = l[i] * corr + rsum;
            m[i] = newm;
#pragma unroll
            for (int j = 0; j < 4; j++) acc[i][j] *= corr;

            *(float4*)&Ps[(ty * 8 + i) * KV_ST + tx * 4] =
                make_float4(s[i][0], s[i][1], s[i][2], s[i][3]);
        }
        __syncthreads();

        // O += P @ V
#pragma unroll 4
        for (int k = 0; k < 64; k++) {
            float4 vv = *(float4*)&Vs[k * KV_ST + tx * 4];
#pragma unroll
            for (int i = 0; i < 8; i++) {
                float p = Ps[(ty * 8 + i) * KV_ST + k];
                acc[i][0] += p * vv.x;
                acc[i][1] += p * vv.y;
                acc[i][2] += p * vv.z;
                acc[i][3] += p * vv.w;
            }
        }
    }

    // epilogue: write [b*Q + q, H*64 + h*64 + d] row-major (ready for Wo GEMM)
    const int HIDcols = H * 64;
#pragma unroll
    for (int i = 0; i < 8; i++) {
        float inv = 1.0f / l[i];
        int gr = b * Q + q0 + ty * 8 + i;
        int gc = h * 64 + tx * 4;
        *(float4*)&Ob[(size_t)gr * HIDcols + gc] =
            make_float4(acc[i][0] * inv, acc[i][1] * inv,
                        acc[i][2] * inv, acc[i][3] * inv);
    }
}

// ---------------------------------------------------------------------------
extern "C" void kernel_launch(void* const* d_in, const int* in_sizes, int n_in,
                              void* d_out, int out_size)
{
    const float* X  = (const float*)d_in[0];
    // d_in[1] = attention_mask (always causal; not read)
    const float* Wq = (const float*)d_in[2];
    const float* Wk = (const float*)d_in[3];
    const float* Wv = (const float*)d_in[4];
    const float* Wo = (const float*)d_in[5];
    float* out = (float*)d_out;

    float *qp, *kp, *vp, *ap, *cp, *sp;
    cudaGetSymbolAddress((void**)&qp, g_Q);
    cudaGetSymbolAddress((void**)&kp, g_K);
    cudaGetSymbolAddress((void**)&vp, g_V);
    cudaGetSymbolAddress((void**)&ap, g_A);
    cudaGetSymbolAddress((void**)&cp, g_cos);
    cudaGetSymbolAddress((void**)&sp, g_sin);

    const int M = B_ * QL_;   // 4096

    // RoPE table (independent of GEMMs — launch first)
    rope_table_kernel<<<(QL_ * 32 + 255) / 256, 256>>>(cp, sp, QL_);

    // QKV projections with permuted epilogue -> [b,h,q,d]
    sgemm_kernel<1><<<dim3(HID_ / 128, M / 128), 256>>>(X, Wq, qp, M, NH_ * D_,  HID_, NH_,  QL_);
    sgemm_kernel<1><<<dim3((KVH_ * D_) / 128, M / 128), 256>>>(X, Wk, kp, M, KVH_ * D_, HID_, KVH_, QL_);
    sgemm_kernel<1><<<dim3((KVH_ * D_) / 128, M / 128), 256>>>(X, Wv, vp, M, KVH_ * D_, HID_, KVH_, QL_);

    // RoPE on Q and K (table lookup, memory-bound)
    {
        int totq = B_ * NH_  * QL_ * 32;
        int totk = B_ * KVH_ * QL_ * 32;
        rope_apply_kernel<<<(totq + 255) / 256, 256>>>(qp, cp, sp, QL_, totq);
        rope_apply_kernel<<<(totk + 255) / 256, 256>>>(kp, cp, sp, QL_, totk);
    }

    // Attention
    cudaFuncSetAttribute(attn_kernel,
                         cudaFuncAttributeMaxDynamicSharedMemorySize,
                         ATTN_SMEM_BYTES);
    attn_kernel<<<dim3(QL_ / 128, NH_, B_), 256, ATTN_SMEM_BYTES>>>(
        qp, kp, vp, ap, QL_, NH_, KVH_);

    // Output projection
    sgemm_kernel<0><<<dim3(HID_ / 128, M / 128), 256>>>(ap, Wo, out, M, HID_, HID_, 0, 0);
}

// round 6
// speedup vs baseline: 1.0017x; 1.0017x over previous
#include <cuda_runtime.h>
#include <cuda_bf16.h>
#include <math.h>

// Problem constants
#define B_   2
#define QL_  2048
#define HID_ 2048
#define NH_  32
#define KVH_ 8
#define D_   64

// Scratch (device globals — no allocation allowed)
__device__ float g_Q[(size_t)B_ * NH_  * QL_ * D_];   // [b,h,q,d]
__device__ float g_K[(size_t)B_ * KVH_ * QL_ * D_];
__device__ float g_V[(size_t)B_ * KVH_ * QL_ * D_];
__device__ float g_A[(size_t)B_ * QL_ * HID_];        // attn out, [b*q, h*d] row-major
__device__ float g_cos[QL_ * 32];                     // RoPE tables [t][j]
__device__ float g_sin[QL_ * 32];

// ---------------------------------------------------------------------------
// SGEMM: C[M,N] = A[M,K] @ B[K,N].  BM=BN=128, BK=16, 256 thr, 8x8 per thread.
// Register-prefetch double buffering: tile k+1 GMEM loads issue before the
// FFMA loop of tile k.
// MODE 0: plain row-major C.
// MODE 1: permuted write: row r=(b*QL+t), col c=(h*64+dd) ->
//         C[((b*H+h)*QL + t)*64 + dd]   (head-major layout for attention)
// ---------------------------------------------------------------------------
template<int MODE>
__global__ void __launch_bounds__(256)
sgemm_kernel(const float* __restrict__ A, const float* __restrict__ B,
             float* __restrict__ C, int M, int N, int K, int H, int QL)
{
    __shared__ __align__(16) float As[16][132];
    __shared__ __align__(16) float Bs[16][132];

    const int tid = threadIdx.x;
    const int tx  = tid & 15;
    const int ty  = tid >> 4;
    const int bx  = blockIdx.x;
    const int by  = blockIdx.y;

    const float* Ab = A + (size_t)by * 128 * K;
    const float* Bb = B + (size_t)bx * 128;

    // per-thread load coordinates (invariant across k tiles)
    const int ar0 = (tid)       >> 2, a40 = (tid)       & 3;
    const int ar1 = (tid + 256) >> 2, a41 = (tid + 256) & 3;
    const int br0 = (tid)       >> 5, b40 = (tid)       & 31;
    const int br1 = (tid + 256) >> 5, b41 = (tid + 256) & 31;

    float acc[8][8];
#pragma unroll
    for (int i = 0; i < 8; i++)
#pragma unroll
        for (int j = 0; j < 8; j++) acc[i][j] = 0.f;

    // prefetch tile 0 into registers
    float4 pA0 = *(const float4*)(Ab + (size_t)ar0 * K + a40 * 4);
    float4 pA1 = *(const float4*)(Ab + (size_t)ar1 * K + a41 * 4);
    float4 pB0 = *(const float4*)(Bb + (size_t)br0 * N + b40 * 4);
    float4 pB1 = *(const float4*)(Bb + (size_t)br1 * N + b41 * 4);

    for (int k0 = 0; k0 < K; k0 += 16) {
        // store prefetched tile to SMEM (A transposed)
        As[a40 * 4 + 0][ar0] = pA0.x;
        As[a40 * 4 + 1][ar0] = pA0.y;
        As[a40 * 4 + 2][ar0] = pA0.z;
        As[a40 * 4 + 3][ar0] = pA0.w;
        As[a41 * 4 + 0][ar1] = pA1.x;
        As[a41 * 4 + 1][ar1] = pA1.y;
        As[a41 * 4 + 2][ar1] = pA1.z;
        As[a41 * 4 + 3][ar1] = pA1.w;
        *(float4*)&Bs[br0][b40 * 4] = pB0;
        *(float4*)&Bs[br1][b41 * 4] = pB1;
        __syncthreads();

        // prefetch next tile (overlaps with FFMA loop below)
        if (k0 + 16 < K) {
            pA0 = *(const float4*)(Ab + (size_t)ar0 * K + k0 + 16 + a40 * 4);
            pA1 = *(const float4*)(Ab + (size_t)ar1 * K + k0 + 16 + a41 * 4);
            pB0 = *(const float4*)(Bb + (size_t)(k0 + 16 + br0) * N + b40 * 4);
            pB1 = *(const float4*)(Bb + (size_t)(k0 + 16 + br1) * N + b41 * 4);
        }

#pragma unroll
        for (int k = 0; k < 16; k++) {
            float4 a0 = *(float4*)&As[k][ty * 4];
            float4 a1 = *(float4*)&As[k][ty * 4 + 64];
            float4 b0 = *(float4*)&Bs[k][tx * 4];
            float4 b1 = *(float4*)&Bs[k][tx * 4 + 64];
            float av[8] = {a0.x, a0.y, a0.z, a0.w, a1.x, a1.y, a1.z, a1.w};
            float bv[8] = {b0.x, b0.y, b0.z, b0.w, b1.x, b1.y, b1.z, b1.w};
#pragma unroll
            for (int i = 0; i < 8; i++)
#pragma unroll
                for (int j = 0; j < 8; j++)
                    acc[i][j] += av[i] * bv[j];
        }
        __syncthreads();
    }

    // epilogue
#pragma unroll
    for (int ih = 0; ih < 2; ih++)
#pragma unroll
        for (int i = 0; i < 4; i++) {
            int gr = by * 128 + ty * 4 + i + ih * 64;
#pragma unroll
            for (int jh = 0; jh < 2; jh++) {
                int gc = bx * 128 + tx * 4 + jh * 64;
                float4 v = make_float4(acc[ih * 4 + i][jh * 4 + 0],
                                       acc[ih * 4 + i][jh * 4 + 1],
                                       acc[ih * 4 + i][jh * 4 + 2],
                                       acc[ih * 4 + i][jh * 4 + 3]);
                if (MODE == 0) {
                    *(float4*)&C[(size_t)gr * N + gc] = v;
                } else {
                    int b = gr / QL, t = gr % QL;
                    int h = gc >> 6, dd = gc & 63;
                    size_t o = (((size_t)b * H + h) * QL + t) * (size_t)64 + dd;
                    *(float4*)&C[o] = v;
                }
            }
        }
}

// ---------------------------------------------------------------------------
// RoPE cos/sin table: one entry per (t, j), computed ONCE in fp64.
// --use_fast_math breaks sincosf for args ~2000 rad; fp64 sincos of the
// reference's fp32 angle matches jnp to ~1e-7. Only 65536 entries -> ~10us.
// ---------------------------------------------------------------------------
__global__ void rope_table_kernel(float* __restrict__ ct, float* __restrict__ st,
                                  int Q)
{
    int idx = blockIdx.x * blockDim.x + threadIdx.x;
    if (idx >= Q * 32) return;
    int j = idx & 31;
    int t = idx >> 5;
    float freq = (float)(1.0 / pow(10000.0, (double)(2 * j) / 64.0));
    float ang  = (float)t * freq;      // fp32 rounding, same as reference
    double cd, sd;
    sincos((double)ang, &sd, &cd);
    ct[idx] = (float)cd;
    st[idx] = (float)sd;
}

// RoPE apply, in-place on [B, H, Q, 64]: memory-bound table lookup.
__global__ void rope_apply_kernel(float* __restrict__ buf,
                                  const float* __restrict__ ct,
                                  const float* __restrict__ st,
                                  int Q, int total)
{
    int idx = blockIdx.x * blockDim.x + threadIdx.x;
    if (idx >= total) return;
    int j  = idx & 31;
    int t  = (idx >> 5) % Q;
    int bh = idx / (32 * Q);
    size_t base = ((size_t)bh * Q + t) * 64;

    float c = ct[(t << 5) + j];
    float s = st[(t << 5) + j];

    float x1 = buf[base + j];
    float x2 = buf[base + j + 32];
    buf[base + j]      = x1 * c - x2 * s;
    buf[base + j + 32] = x2 * c + x1 * s;
}

// ---------------------------------------------------------------------------
// Causal flash attention with GQA.
// Grid: (Q/128, NH, B). 256 threads. BQ=128, BK=64, D=64.
// ---------------------------------------------------------------------------
#define QT_ST 132
#define KV_ST 68
#define ATTN_SMEM_FLOATS (64 * QT_ST + 64 * KV_ST + 64 * KV_ST + 128 * KV_ST)
#define ATTN_SMEM_BYTES  (ATTN_SMEM_FLOATS * 4)

__global__ void __launch_bounds__(256)
attn_kernel(const float* __restrict__ Qb, const float* __restrict__ Kb,
            const float* __restrict__ Vb, float* __restrict__ Ob,
            int Q, int H, int KVH)
{
    extern __shared__ float sm[];
    float* Qt = sm;                        // [64][QT_ST]
    float* Kt = Qt + 64 * QT_ST;           // [64][KV_ST]
    float* Vs = Kt + 64 * KV_ST;           // [64][KV_ST]
    float* Ps = Vs + 64 * KV_ST;           // [128][KV_ST]

    const int tid = threadIdx.x;
    const int tx  = tid & 15;
    const int ty  = tid >> 4;
    const int qt  = blockIdx.x;
    const int h   = blockIdx.y;
    const int b   = blockIdx.z;
    const int kvh = h / (H / KVH);
    const int q0  = qt * 128;

    const float* Qg = Qb + (((size_t)b * H + h) * Q + q0) * 64;
    const float* Kg = Kb + (((size_t)b * KVH + kvh) * Q) * 64;
    const float* Vg = Vb + (((size_t)b * KVH + kvh) * Q) * 64;

    // load Q tile (128x64) -> Qt[d][r]
#pragma unroll
    for (int it = 0; it < 8; it++) {
        int f  = tid + it * 256;   // 0..2047 float4s
        int r  = f >> 4;
        int d4 = f & 15;
        float4 v = *(const float4*)(Qg + (size_t)r * 64 + d4 * 4);
        Qt[(d4 * 4 + 0) * QT_ST + r] = v.x;
        Qt[(d4 * 4 + 1) * QT_ST + r] = v.y;
        Qt[(d4 * 4 + 2) * QT_ST + r] = v.z;
        Qt[(d4 * 4 + 3) * QT_ST + r] = v.w;
    }

    float m[8], l[8], acc[8][4];
#pragma unroll
    for (int i = 0; i < 8; i++) {
        m[i] = -1e30f;
        l[i] = 0.f;
#pragma unroll
        for (int j = 0; j < 4; j++) acc[i][j] = 0.f;
    }

    const int ktiles = (q0 + 128) / 64;   // causal: only tiles up to the diagonal
    const float scale = 0.125f;           // 1/sqrt(64)

    for (int kt = 0; kt < ktiles; kt++) {
        const int k0 = kt * 64;
        __syncthreads();   // previous iteration's readers done (also after Q load)

        // load K tile (64x64) -> Kt[d][c] ; V tile (64x64) -> Vs[c][d]
#pragma unroll
        for (int it = 0; it < 4; it++) {
            int f  = tid + it * 256;   // 0..1023 float4s
            int c  = f >> 4;
            int d4 = f & 15;
            float4 kv = *(const float4*)(Kg + (size_t)(k0 + c) * 64 + d4 * 4);
            Kt[(d4 * 4 + 0) * KV_ST + c] = kv.x;
            Kt[(d4 * 4 + 1) * KV_ST + c] = kv.y;
            Kt[(d4 * 4 + 2) * KV_ST + c] = kv.z;
            Kt[(d4 * 4 + 3) * KV_ST + c] = kv.w;
            float4 vv = *(const float4*)(Vg + (size_t)(k0 + c) * 64 + d4 * 4);
            *(float4*)&Vs[c * KV_ST + d4 * 4] = vv;
        }
        __syncthreads();

        // S = Q K^T  (8 rows x 4 cols per thread)
        float s[8][4];
#pragma unroll
        for (int i = 0; i < 8; i++)
#pragma unroll
            for (int j = 0; j < 4; j++) s[i][j] = 0.f;

#pragma unroll 4
        for (int d = 0; d < 64; d++) {
            float4 q0v = *(float4*)&Qt[d * QT_ST + ty * 8];
            float4 q1v = *(float4*)&Qt[d * QT_ST + ty * 8 + 4];
            float4 kv  = *(float4*)&Kt[d * KV_ST + tx * 4];
            float qv[8] = {q0v.x, q0v.y, q0v.z, q0v.w, q1v.x, q1v.y, q1v.z, q1v.w};
            float kvv[4] = {kv.x, kv.y, kv.z, kv.w};
#pragma unroll
            for (int i = 0; i < 8; i++)
#pragma unroll
                for (int j = 0; j < 4; j++)
                    s[i][j] += qv[i] * kvv[j];
        }

        // scale + causal mask + online softmax
#pragma unroll
        for (int i = 0; i < 8; i++) {
            int qg = q0 + ty * 8 + i;
            float rm = -1e30f;
#pragma unroll
            for (int j = 0; j < 4; j++) {
                int kg = k0 + tx * 4 + j;
                float v = s[i][j] * scale;
                if (kg > qg) v = -1e30f;
                s[i][j] = v;
                rm = fmaxf(rm, v);
            }
#pragma unroll
            for (int off = 8; off; off >>= 1)
                rm = fmaxf(rm, __shfl_xor_sync(0xffffffffu, rm, off));

            float newm = fmaxf(m[i], rm);
            float corr = __expf(m[i] - newm);
            float rsum = 0.f;
#pragma unroll
            for (int j = 0; j < 4; j++) {
                float p = __expf(s[i][j] - newm);
                s[i][j] = p;
                rsum += p;
            }
#pragma unroll
            for (int off = 8; off; off >>= 1)
                rsum += __shfl_xor_sync(0xffffffffu, rsum, off);

            l[i] = l[i] * corr + rsum;
            m[i] = newm;
#pragma unroll
            for (int j = 0; j < 4; j++) acc[i][j] *= corr;

            *(float4*)&Ps[(ty * 8 + i) * KV_ST + tx * 4] =
                make_float4(s[i][0], s[i][1], s[i][2], s[i][3]);
        }
        __syncthreads();

        // O += P @ V
#pragma unroll 4
        for (int k = 0; k < 64; k++) {
            float4 vv = *(float4*)&Vs[k * KV_ST + tx * 4];
#pragma unroll
            for (int i = 0; i < 8; i++) {
                float p = Ps[(ty * 8 + i) * KV_ST + k];
                acc[i][0] += p * vv.x;
                acc[i][1] += p * vv.y;
                acc[i][2] += p * vv.z;
                acc[i][3] += p * vv.w;
            }
        }
    }

    // epilogue: write [b*Q + q, H*64 + h*64 + d] row-major (ready for Wo GEMM)
    const int HIDcols = H * 64;
#pragma unroll
    for (int i = 0; i < 8; i++) {
        float inv = 1.0f / l[i];
        int gr = b * Q + q0 + ty * 8 + i;
        int gc = h * 64 + tx * 4;
        *(float4*)&Ob[(size_t)gr * HIDcols + gc] =
            make_float4(acc[i][0] * inv, acc[i][1] * inv,
                        acc[i][2] * inv, acc[i][3] * inv);
    }
}

// ---------------------------------------------------------------------------
extern "C" void kernel_launch(void* const* d_in, const int* in_sizes, int n_in,
                              void* d_out, int out_size)
{
    const float* X  = (const float*)d_in[0];
    // d_in[1] = attention_mask (always causal; not read)
    const float* Wq = (const float*)d_in[2];
    const float* Wk = (const float*)d_in[3];
    const float* Wv = (const float*)d_in[4];
    const float* Wo = (const float*)d_in[5];
    float* out = (float*)d_out;

    float *qp, *kp, *vp, *ap, *cp, *sp;
    cudaGetSymbolAddress((void**)&qp, g_Q);
    cudaGetSymbolAddress((void**)&kp, g_K);
    cudaGetSymbolAddress((void**)&vp, g_V);
    cudaGetSymbolAddress((void**)&ap, g_A);
    cudaGetSymbolAddress((void**)&cp, g_cos);
    cudaGetSymbolAddress((void**)&sp, g_sin);

    const int M = B_ * QL_;   // 4096

    // RoPE table (independent of GEMMs — launch first)
    rope_table_kernel<<<(QL_ * 32 + 255) / 256, 256>>>(cp, sp, QL_);

    // QKV projections with permuted epilogue -> [b,h,q,d]
    sgemm_kernel<1><<<dim3(HID_ / 128, M / 128), 256>>>(X, Wq, qp, M, NH_ * D_,  HID_, NH_,  QL_);
    sgemm_kernel<1><<<dim3((KVH_ * D_) / 128, M / 128), 256>>>(X, Wk, kp, M, KVH_ * D_, HID_, KVH_, QL_);
    sgemm_kernel<1><<<dim3((KVH_ * D_) / 128, M / 128), 256>>>(X, Wv, vp, M, KVH_ * D_, HID_, KVH_, QL_);

    // RoPE on Q and K (table lookup, memory-bound)
    {
        int totq = B_ * NH_  * QL_ * 32;
        int totk = B_ * KVH_ * QL_ * 32;
        rope_apply_kernel<<<(totq + 255) / 256, 256>>>(qp, cp, sp, QL_, totq);
        rope_apply_kernel<<<(totk + 255) / 256, 256>>>(kp, cp, sp, QL_, totk);
    }

    // Attention
    cudaFuncSetAttribute(attn_kernel,
                         cudaFuncAttributeMaxDynamicSharedMemorySize,
                         ATTN_SMEM_BYTES);
    attn_kernel<<<dim3(QL_ / 128, NH_, B_), 256, ATTN_SMEM_BYTES>>>(
        qp, kp, vp, ap, QL_, NH_, KVH_);

    // Output projection
    sgemm_kernel<0><<<dim3(HID_ / 128, M / 128), 256>>>(ap, Wo, out, M, HID_, HID_, 0, 0);
}

// round 7
// speedup vs baseline: 1.0041x; 1.0024x over previous
#include <cuda_runtime.h>
#include <cuda_bf16.h>
#include <math.h>

// Problem constants
#define B_   2
#define QL_  2048
#define HID_ 2048
#define NH_  32
#define KVH_ 8
#define D_   64

// Scratch (device globals — no allocation allowed)
__device__ float g_Q[(size_t)B_ * NH_  * QL_ * D_];   // [b,h,q,d]
__device__ float g_K[(size_t)B_ * KVH_ * QL_ * D_];
__device__ float g_V[(size_t)B_ * KVH_ * QL_ * D_];
__device__ float g_A[(size_t)B_ * QL_ * HID_];        // attn out, [b*q, h*d] row-major
__device__ float g_cos[QL_ * 32];                     // RoPE tables [t][j]
__device__ float g_sin[QL_ * 32];

// ---------------------------------------------------------------------------
// SGEMM: C[M,N] = A[M,K] @ B[K,N].  BM=BN=128, BK=16, 256 thr, 8x8 per thread.
// Register-prefetch double buffering: tile k+1 GMEM loads issue before the
// FFMA loop of tile k.
// MODE 0: plain row-major C.
// MODE 1: permuted write: row r=(b*QL+t), col c=(h*64+dd) ->
//         C[((b*H+h)*QL + t)*64 + dd]   (head-major layout for attention)
// ---------------------------------------------------------------------------
template<int MODE>
__global__ void __launch_bounds__(256)
sgemm_kernel(const float* __restrict__ A, const float* __restrict__ B,
             float* __restrict__ C, int M, int N, int K, int H, int QL)
{
    __shared__ __align__(16) float As[16][132];
    __shared__ __align__(16) float Bs[16][132];

    const int tid = threadIdx.x;
    const int tx  = tid & 15;
    const int ty  = tid >> 4;
    const int bx  = blockIdx.x;
    const int by  = blockIdx.y;

    const float* Ab = A + (size_t)by * 128 * K;
    const float* Bb = B + (size_t)bx * 128;

    // per-thread load coordinates (invariant across k tiles)
    const int ar0 = (tid)       >> 2, a40 = (tid)       & 3;
    const int ar1 = (tid + 256) >> 2, a41 = (tid + 256) & 3;
    const int br0 = (tid)       >> 5, b40 = (tid)       & 31;
    const int br1 = (tid + 256) >> 5, b41 = (tid + 256) & 31;

    float acc[8][8];
#pragma unroll
    for (int i = 0; i < 8; i++)
#pragma unroll
        for (int j = 0; j < 8; j++) acc[i][j] = 0.f;

    // prefetch tile 0 into registers
    float4 pA0 = *(const float4*)(Ab + (size_t)ar0 * K + a40 * 4);
    float4 pA1 = *(const float4*)(Ab + (size_t)ar1 * K + a41 * 4);
    float4 pB0 = *(const float4*)(Bb + (size_t)br0 * N + b40 * 4);
    float4 pB1 = *(const float4*)(Bb + (size_t)br1 * N + b41 * 4);

    for (int k0 = 0; k0 < K; k0 += 16) {
        // store prefetched tile to SMEM (A transposed)
        As[a40 * 4 + 0][ar0] = pA0.x;
        As[a40 * 4 + 1][ar0] = pA0.y;
        As[a40 * 4 + 2][ar0] = pA0.z;
        As[a40 * 4 + 3][ar0] = pA0.w;
        As[a41 * 4 + 0][ar1] = pA1.x;
        As[a41 * 4 + 1][ar1] = pA1.y;
        As[a41 * 4 + 2][ar1] = pA1.z;
        As[a41 * 4 + 3][ar1] = pA1.w;
        *(float4*)&Bs[br0][b40 * 4] = pB0;
        *(float4*)&Bs[br1][b41 * 4] = pB1;
        __syncthreads();

        // prefetch next tile (overlaps with FFMA loop below)
        if (k0 + 16 < K) {
            pA0 = *(const float4*)(Ab + (size_t)ar0 * K + k0 + 16 + a40 * 4);
            pA1 = *(const float4*)(Ab + (size_t)ar1 * K + k0 + 16 + a41 * 4);
            pB0 = *(const float4*)(Bb + (size_t)(k0 + 16 + br0) * N + b40 * 4);
            pB1 = *(const float4*)(Bb + (size_t)(k0 + 16 + br1) * N + b41 * 4);
        }

#pragma unroll
        for (int k = 0; k < 16; k++) {
            float4 a0 = *(float4*)&As[k][ty * 4];
            float4 a1 = *(float4*)&As[k][ty * 4 + 64];
            float4 b0 = *(float4*)&Bs[k][tx * 4];
            float4 b1 = *(float4*)&Bs[k][tx * 4 + 64];
            float av[8] = {a0.x, a0.y, a0.z, a0.w, a1.x, a1.y, a1.z, a1.w};
            float bv[8] = {b0.x, b0.y, b0.z, b0.w, b1.x, b1.y, b1.z, b1.w};
#pragma unroll
            for (int i = 0; i < 8; i++)
#pragma unroll
                for (int j = 0; j < 8; j++)
                    acc[i][j] += av[i] * bv[j];
        }
        __syncthreads();
    }

    // epilogue
#pragma unroll
    for (int ih = 0; ih < 2; ih++)
#pragma unroll
        for (int i = 0; i < 4; i++) {
            int gr = by * 128 + ty * 4 + i + ih * 64;
#pragma unroll
            for (int jh = 0; jh < 2; jh++) {
                int gc = bx * 128 + tx * 4 + jh * 64;
                float4 v = make_float4(acc[ih * 4 + i][jh * 4 + 0],
                                       acc[ih * 4 + i][jh * 4 + 1],
                                       acc[ih * 4 + i][jh * 4 + 2],
                                       acc[ih * 4 + i][jh * 4 + 3]);
                if (MODE == 0) {
                    *(float4*)&C[(size_t)gr * N + gc] = v;
                } else {
                    int b = gr / QL, t = gr % QL;
                    int h = gc >> 6, dd = gc & 63;
                    size_t o = (((size_t)b * H + h) * QL + t) * (size_t)64 + dd;
                    *(float4*)&C[o] = v;
                }
            }
        }
}

// ---------------------------------------------------------------------------
// RoPE cos/sin table: one entry per (t, j), computed ONCE in fp64.
// --use_fast_math breaks sincosf for args ~2000 rad; fp64 sincos of the
// reference's fp32 angle matches jnp to ~1e-7. Only 65536 entries -> ~10us.
// ---------------------------------------------------------------------------
__global__ void rope_table_kernel(float* __restrict__ ct, float* __restrict__ st,
                                  int Q)
{
    int idx = blockIdx.x * blockDim.x + threadIdx.x;
    if (idx >= Q * 32) return;
    int j = idx & 31;
    int t = idx >> 5;
    float freq = (float)(1.0 / pow(10000.0, (double)(2 * j) / 64.0));
    float ang  = (float)t * freq;      // fp32 rounding, same as reference
    double cd, sd;
    sincos((double)ang, &sd, &cd);
    ct[idx] = (float)cd;
    st[idx] = (float)sd;
}

// RoPE apply, in-place on [B, H, Q, 64]: memory-bound table lookup.
__global__ void rope_apply_kernel(float* __restrict__ buf,
                                  const float* __restrict__ ct,
                                  const float* __restrict__ st,
                                  int Q, int total)
{
    int idx = blockIdx.x * blockDim.x + threadIdx.x;
    if (idx >= total) return;
    int j  = idx & 31;
    int t  = (idx >> 5) % Q;
    int bh = idx / (32 * Q);
    size_t base = ((size_t)bh * Q + t) * 64;

    float c = ct[(t << 5) + j];
    float s = st[(t << 5) + j];

    float x1 = buf[base + j];
    float x2 = buf[base + j + 32];
    buf[base + j]      = x1 * c - x2 * s;
    buf[base + j + 32] = x2 * c + x1 * s;
}

// ---------------------------------------------------------------------------
// Causal flash attention with GQA.
// Grid: (Q/128, NH, B). 256 threads. BQ=128, BK=64, D=64.
// ---------------------------------------------------------------------------
#define QT_ST 132
#define KV_ST 68
#define ATTN_SMEM_FLOATS (64 * QT_ST + 64 * KV_ST + 64 * KV_ST + 128 * KV_ST)
#define ATTN_SMEM_BYTES  (ATTN_SMEM_FLOATS * 4)

__global__ void __launch_bounds__(256)
attn_kernel(const float* __restrict__ Qb, const float* __restrict__ Kb,
            const float* __restrict__ Vb, float* __restrict__ Ob,
            int Q, int H, int KVH)
{
    extern __shared__ float sm[];
    float* Qt = sm;                        // [64][QT_ST]
    float* Kt = Qt + 64 * QT_ST;           // [64][KV_ST]
    float* Vs = Kt + 64 * KV_ST;           // [64][KV_ST]
    float* Ps = Vs + 64 * KV_ST;           // [128][KV_ST]

    const int tid = threadIdx.x;
    const int tx  = tid & 15;
    const int ty  = tid >> 4;
    const int qt  = blockIdx.x;
    const int h   = blockIdx.y;
    const int b   = blockIdx.z;
    const int kvh = h / (H / KVH);
    const int q0  = qt * 128;

    const float* Qg = Qb + (((size_t)b * H + h) * Q + q0) * 64;
    const float* Kg = Kb + (((size_t)b * KVH + kvh) * Q) * 64;
    const float* Vg = Vb + (((size_t)b * KVH + kvh) * Q) * 64;

    // load Q tile (128x64) -> Qt[d][r]
#pragma unroll
    for (int it = 0; it < 8; it++) {
        int f  = tid + it * 256;   // 0..2047 float4s
        int r  = f >> 4;
        int d4 = f & 15;
        float4 v = *(const float4*)(Qg + (size_t)r * 64 + d4 * 4);
        Qt[(d4 * 4 + 0) * QT_ST + r] = v.x;
        Qt[(d4 * 4 + 1) * QT_ST + r] = v.y;
        Qt[(d4 * 4 + 2) * QT_ST + r] = v.z;
        Qt[(d4 * 4 + 3) * QT_ST + r] = v.w;
    }

    float m[8], l[8], acc[8][4];
#pragma unroll
    for (int i = 0; i < 8; i++) {
        m[i] = -1e30f;
        l[i] = 0.f;
#pragma unroll
        for (int j = 0; j < 4; j++) acc[i][j] = 0.f;
    }

    const int ktiles = (q0 + 128) / 64;   // causal: only tiles up to the diagonal
    const float scale = 0.125f;           // 1/sqrt(64)

    for (int kt = 0; kt < ktiles; kt++) {
        const int k0 = kt * 64;
        __syncthreads();   // previous iteration's readers done (also after Q load)

        // load K tile (64x64) -> Kt[d][c] ; V tile (64x64) -> Vs[c][d]
#pragma unroll
        for (int it = 0; it < 4; it++) {
            int f  = tid + it * 256;   // 0..1023 float4s
            int c  = f >> 4;
            int d4 = f & 15;
            float4 kv = *(const float4*)(Kg + (size_t)(k0 + c) * 64 + d4 * 4);
            Kt[(d4 * 4 + 0) * KV_ST + c] = kv.x;
            Kt[(d4 * 4 + 1) * KV_ST + c] = kv.y;
            Kt[(d4 * 4 + 2) * KV_ST + c] = kv.z;
            Kt[(d4 * 4 + 3) * KV_ST + c] = kv.w;
            float4 vv = *(const float4*)(Vg + (size_t)(k0 + c) * 64 + d4 * 4);
            *(float4*)&Vs[c * KV_ST + d4 * 4] = vv;
        }
        __syncthreads();

        // S = Q K^T  (8 rows x 4 cols per thread)
        float s[8][4];
#pragma unroll
        for (int i = 0; i < 8; i++)
#pragma unroll
            for (int j = 0; j < 4; j++) s[i][j] = 0.f;

#pragma unroll 4
        for (int d = 0; d < 64; d++) {
            float4 q0v = *(float4*)&Qt[d * QT_ST + ty * 8];
            float4 q1v = *(float4*)&Qt[d * QT_ST + ty * 8 + 4];
            float4 kv  = *(float4*)&Kt[d * KV_ST + tx * 4];
            float qv[8] = {q0v.x, q0v.y, q0v.z, q0v.w, q1v.x, q1v.y, q1v.z, q1v.w};
            float kvv[4] = {kv.x, kv.y, kv.z, kv.w};
#pragma unroll
            for (int i = 0; i < 8; i++)
#pragma unroll
                for (int j = 0; j < 4; j++)
                    s[i][j] += qv[i] * kvv[j];
        }

        // scale + causal mask + online softmax
#pragma unroll
        for (int i = 0; i < 8; i++) {
            int qg = q0 + ty * 8 + i;
            float rm = -1e30f;
#pragma unroll
            for (int j = 0; j < 4; j++) {
                int kg = k0 + tx * 4 + j;
                float v = s[i][j] * scale;
                if (kg > qg) v = -1e30f;
                s[i][j] = v;
                rm = fmaxf(rm, v);
            }
#pragma unroll
            for (int off = 8; off; off >>= 1)
                rm = fmaxf(rm, __shfl_xor_sync(0xffffffffu, rm, off));

            float newm = fmaxf(m[i], rm);
            float corr = __expf(m[i] - newm);
            float rsum = 0.f;
#pragma unroll
            for (int j = 0; j < 4; j++) {
                float p = __expf(s[i][j] - newm);
                s[i][j] = p;
                rsum += p;
            }
#pragma unroll
            for (int off = 8; off; off >>= 1)
                rsum += __shfl_xor_sync(0xffffffffu, rsum, off);

            l[i] = l[i] * corr + rsum;
            m[i] = newm;
#pragma unroll
            for (int j = 0; j < 4; j++) acc[i][j] *= corr;

            *(float4*)&Ps[(ty * 8 + i) * KV_ST + tx * 4] =
                make_float4(s[i][0], s[i][1], s[i][2], s[i][3]);
        }
        __syncthreads();

        // O += P @ V
#pragma unroll 4
        for (int k = 0; k < 64; k++) {
            float4 vv = *(float4*)&Vs[k * KV_ST + tx * 4];
#pragma unroll
            for (int i = 0; i < 8; i++) {
                float p = Ps[(ty * 8 + i) * KV_ST + k];
                acc[i][0] += p * vv.x;
                acc[i][1] += p * vv.y;
                acc[i][2] += p * vv.z;
                acc[i][3] += p * vv.w;
            }
        }
    }

    // epilogue: write [b*Q + q, H*64 + h*64 + d] row-major (ready for Wo GEMM)
    const int HIDcols = H * 64;
#pragma unroll
    for (int i = 0; i < 8; i++) {
        float inv = 1.0f / l[i];
        int gr = b * Q + q0 + ty * 8 + i;
        int gc = h * 64 + tx * 4;
        *(float4*)&Ob[(size_t)gr * HIDcols + gc] =
            make_float4(acc[i][0] * inv, acc[i][1] * inv,
                        acc[i][2] * inv, acc[i][3] * inv);
    }
}

// ---------------------------------------------------------------------------
extern "C" void kernel_launch(void* const* d_in, const int* in_sizes, int n_in,
                              void* d_out, int out_size)
{
    const float* X  = (const float*)d_in[0];
    // d_in[1] = attention_mask (always causal; not read)
    const float* Wq = (const float*)d_in[2];
    const float* Wk = (const float*)d_in[3];
    const float* Wv = (const float*)d_in[4];
    const float* Wo = (const float*)d_in[5];
    float* out = (float*)d_out;

    float *qp, *kp, *vp, *ap, *cp, *sp;
    cudaGetSymbolAddress((void**)&qp, g_Q);
    cudaGetSymbolAddress((void**)&kp, g_K);
    cudaGetSymbolAddress((void**)&vp, g_V);
    cudaGetSymbolAddress((void**)&ap, g_A);
    cudaGetSymbolAddress((void**)&cp, g_cos);
    cudaGetSymbolAddress((void**)&sp, g_sin);

    const int M = B_ * QL_;   // 4096

    // RoPE table (independent of GEMMs — launch first)
    rope_table_kernel<<<(QL_ * 32 + 255) / 256, 256>>>(cp, sp, QL_);

    // QKV projections with permuted epilogue -> [b,h,q,d]
    sgemm_kernel<1><<<dim3(HID_ / 128, M / 128), 256>>>(X, Wq, qp, M, NH_ * D_,  HID_, NH_,  QL_);
    sgemm_kernel<1><<<dim3((KVH_ * D_) / 128, M / 128), 256>>>(X, Wk, kp, M, KVH_ * D_, HID_, KVH_, QL_);
    sgemm_kernel<1><<<dim3((KVH_ * D_) / 128, M / 128), 256>>>(X, Wv, vp, M, KVH_ * D_, HID_, KVH_, QL_);

    // RoPE on Q and K (table lookup, memory-bound)
    {
        int totq = B_ * NH_  * QL_ * 32;
        int totk = B_ * KVH_ * QL_ * 32;
        rope_apply_kernel<<<(totq + 255) / 256, 256>>>(qp, cp, sp, QL_, totq);
        rope_apply_kernel<<<(totk + 255) / 256, 256>>>(kp, cp, sp, QL_, totk);
    }

    // Attention
    cudaFuncSetAttribute(attn_kernel,
                         cudaFuncAttributeMaxDynamicSharedMemorySize,
                         ATTN_SMEM_BYTES);
    attn_kernel<<<dim3(QL_ / 128, NH_, B_), 256, ATTN_SMEM_BYTES>>>(
        qp, kp, vp, ap, QL_, NH_, KVH_);

    // Output projection
    sgemm_kernel<0><<<dim3(HID_ / 128, M / 128), 256>>>(ap, Wo, out, M, HID_, HID_, 0, 0);
}

// round 9
// speedup vs baseline: 1.5242x; 1.5180x over previous
#include <cuda_runtime.h>
#include <cuda_bf16.h>
#include <math.h>
#include <stdint.h>

// Problem constants
#define B_   2
#define QL_  2048
#define HID_ 2048
#define NH_  32
#define KVH_ 8
#define D_   64

// ===========================================================================
// PTX helpers — BASE PTX ONLY (harness targets plain sm_103: no tcgen05!)
// ===========================================================================
__device__ __forceinline__ uint32_t smem_u32(const void* p) {
    uint32_t a;
    asm("{ .reg .u64 t; cvta.to.shared.u64 t, %1; cvt.u32.u64 %0, t; }"
        : "=r"(a) : "l"(p));
    return a;
}
__device__ __forceinline__ void ldmat_x4(uint32_t* r, uint32_t addr) {
    asm volatile("ldmatrix.sync.aligned.m8n8.x4.shared.b16 {%0,%1,%2,%3}, [%4];"
                 : "=r"(r[0]), "=r"(r[1]), "=r"(r[2]), "=r"(r[3]) : "r"(addr));
}
__device__ __forceinline__ void ldmat_x2(uint32_t* r, uint32_t addr) {
    asm volatile("ldmatrix.sync.aligned.m8n8.x2.shared.b16 {%0,%1}, [%2];"
                 : "=r"(r[0]), "=r"(r[1]) : "r"(addr));
}
__device__ __forceinline__ void mma_bf16(float* d, const uint32_t* a, const uint32_t* b) {
    asm volatile("mma.sync.aligned.m16n8k16.row.col.f32.bf16.bf16.f32 "
                 "{%0,%1,%2,%3}, {%4,%5,%6,%7}, {%8,%9}, {%0,%1,%2,%3};"
                 : "+f"(d[0]), "+f"(d[1]), "+f"(d[2]), "+f"(d[3])
                 : "r"(a[0]), "r"(a[1]), "r"(a[2]), "r"(a[3]),
                   "r"(b[0]), "r"(b[1]));
}
__device__ __forceinline__ void cp_async16(uint32_t dst, const void* src) {
    asm volatile("cp.async.cg.shared.global [%0], [%1], 16;"
                 :: "r"(dst), "l"(src));
}
#define CP_COMMIT()  asm volatile("cp.async.commit_group;" ::: "memory")
#define CP_WAIT(n)   asm volatile("cp.async.wait_group %0;" :: "n"(n) : "memory")

// ===========================================================================
// Scratch (device globals — no allocation allowed)
// ===========================================================================
__device__ float g_Q[(size_t)B_ * NH_  * QL_ * D_];   // [b,h,q,d] fp32
__device__ float g_K[(size_t)B_ * KVH_ * QL_ * D_];
__device__ float g_V[(size_t)B_ * KVH_ * QL_ * D_];
__device__ float g_cos[QL_ * 32];
__device__ float g_sin[QL_ * 32];
// bf16 split operands
__device__ __nv_bfloat16 g_Xhi[(size_t)B_ * QL_ * HID_];   // X split  [M,K]
__device__ __nv_bfloat16 g_Xlo[(size_t)B_ * QL_ * HID_];
__device__ __nv_bfloat16 g_Whi[(size_t)3072 * HID_];       // Wq|Wk|Wv transposed [N,K]
__device__ __nv_bfloat16 g_Wlo[(size_t)3072 * HID_];
__device__ __nv_bfloat16 g_Ohi[(size_t)HID_ * HID_];       // Wo transposed [N,K]
__device__ __nv_bfloat16 g_Olo[(size_t)HID_ * HID_];
__device__ __nv_bfloat16 g_Ahi[(size_t)B_ * QL_ * HID_];   // attn out split [M,K]
__device__ __nv_bfloat16 g_Alo[(size_t)B_ * QL_ * HID_];

// ===========================================================================
// Elementwise fp32 -> (bf16 hi, bf16 lo) split
// ===========================================================================
__global__ void split_kernel(const float* __restrict__ src,
                             __nv_bfloat16* __restrict__ hi,
                             __nv_bfloat16* __restrict__ lo, int n)
{
    int i = blockIdx.x * blockDim.x + threadIdx.x;
    if (i >= n) return;
    float v = src[i];
    __nv_bfloat16 h = __float2bfloat16(v);
    hi[i] = h;
    lo[i] = __float2bfloat16(v - __bfloat162float(h));
}

// Transpose + split: W[K, Ncols] -> T[(rowOffset+n), k] bf16 hi/lo, ldT = K.
__global__ void transpose_split_kernel(const float* __restrict__ W,
                                       __nv_bfloat16* __restrict__ Thi,
                                       __nv_bfloat16* __restrict__ Tlo,
                                       int K, int Ncols, int rowOffset)
{
    __shared__ float tile[32][33];
    int k0 = blockIdx.y * 32, n0 = blockIdx.x * 32;
    int tx = threadIdx.x, ty = threadIdx.y;    // (32, 8)
#pragma unroll
    for (int i = 0; i < 4; i++) {
        int k = k0 + ty + i * 8;
        tile[ty + i * 8][tx] = W[(size_t)k * Ncols + n0 + tx];
    }
    __syncthreads();
#pragma unroll
    for (int i = 0; i < 4; i++) {
        int n = n0 + ty + i * 8;
        float v = tile[tx][ty + i * 8];
        __nv_bfloat16 h = __float2bfloat16(v);
        size_t o = (size_t)(rowOffset + n) * K + k0 + tx;
        Thi[o] = h;
        Tlo[o] = __float2bfloat16(v - __bfloat162float(h));
    }
}

// ===========================================================================
// mma.sync bf16x3 GEMM:  C[M,N] = A[M,K] @ B^T  (B stored [N,K]).
// CTA tile 128x128, 8 warps (2x4), warp tile 64x32 via m16n8k16.
// K-chunks of 64, 2-stage cp.async double buffer.
// SMEM row stride 144B -> conflict-free ldmatrix.
// MODE 0: plain row-major C0.  MODE 1: QKV head scatter (C0=Q, C1=K, C2=V).
// ===========================================================================
#define TILE_B   18432                       // 128 rows * 144B
#define STAGE_B  (4 * TILE_B)                // Ahi, Alo, Bhi, Blo
#define MMA_SMEM_BYTES (2 * STAGE_B)         // 147456

template<int MODE>
__global__ void __launch_bounds__(256)
mma_gemm(const __nv_bfloat16* __restrict__ Ahi, const __nv_bfloat16* __restrict__ Alo,
         const __nv_bfloat16* __restrict__ Bhi, const __nv_bfloat16* __restrict__ Blo,
         float* __restrict__ C0, float* __restrict__ C1, float* __restrict__ C2,
         int M, int N, int K)
{
    extern __shared__ char smc[];
    const uint32_t sbase = smem_u32(smc);
    const int tid  = threadIdx.x;
    const int wid  = tid >> 5;
    const int lane = tid & 31;
    const int bx   = blockIdx.x;   // N tile
    const int by   = blockIdx.y;   // M tile
    const int wm   = wid >> 2;     // 0..1  (64-row slab)
    const int wn   = wid & 3;      // 0..3  (32-col slab)

    float acc[4][4][4];
#pragma unroll
    for (int mt = 0; mt < 4; mt++)
#pragma unroll
        for (int nt = 0; nt < 4; nt++)
#pragma unroll
            for (int r = 0; r < 4; r++) acc[mt][nt][r] = 0.f;

    const int NC = K >> 6;

    auto load_chunk = [&](int ci, int s) {
        const int k0 = ci * 64;
        const uint32_t sb = sbase + s * STAGE_B;
#pragma unroll
        for (int it = 0; it < 4; it++) {
            int f = tid + it * 256;          // 0..1023
            int r = f >> 3, seg = f & 7;     // row 0..127, 16B segment 0..7
            uint32_t dst = sb + r * 144 + seg * 16;
            size_t ga = (size_t)(by * 128 + r) * K + k0 + seg * 8;
            size_t gb = (size_t)(bx * 128 + r) * K + k0 + seg * 8;
            cp_async16(dst,              Ahi + ga);
            cp_async16(dst + TILE_B,     Alo + ga);
            cp_async16(dst + 2 * TILE_B, Bhi + gb);
            cp_async16(dst + 3 * TILE_B, Blo + gb);
        }
        CP_COMMIT();
    };

    load_chunk(0, 0);

    for (int ci = 0; ci < NC; ci++) {
        const int s = ci & 1;
        if (ci + 1 < NC) { load_chunk(ci + 1, s ^ 1); CP_WAIT(1); }
        else             { CP_WAIT(0); }
        __syncthreads();

        const uint32_t sb    = sbase + s * STAGE_B;
        const uint32_t aBase = sb + wm * 64 * 144;
        const uint32_t bBase = sb + 2 * TILE_B + wn * 32 * 144;

        const int ar = lane & 15;              // A ldmatrix row within 16
        const int acol = (lane >> 4) * 8;      // A ldmatrix col half
        const int br = lane & 7;               // B ldmatrix row within 8
        const int bcol = ((lane >> 3) & 1) * 8;

#pragma unroll
        for (int ks = 0; ks < 4; ks++) {
            const int kc = ks * 16;
            uint32_t ahi[4][4], alo[4][4], bhi[4][2], blo[4][2];
#pragma unroll
            for (int mt = 0; mt < 4; mt++) {
                uint32_t a = aBase + (mt * 16 + ar) * 144 + (kc + acol) * 2;
                ldmat_x4(ahi[mt], a);
                ldmat_x4(alo[mt], a + TILE_B);
            }
#pragma unroll
            for (int nt = 0; nt < 4; nt++) {
                uint32_t b = bBase + (nt * 8 + br) * 144 + (kc + bcol) * 2;
                ldmat_x2(bhi[nt], b);
                ldmat_x2(blo[nt], b + TILE_B);
            }
            // pass-major ordering: same accumulator reused at distance 16
#pragma unroll
            for (int mt = 0; mt < 4; mt++)
#pragma unroll
                for (int nt = 0; nt < 4; nt++)
                    mma_bf16(acc[mt][nt], ahi[mt], bhi[nt]);
#pragma unroll
            for (int mt = 0; mt < 4; mt++)
#pragma unroll
                for (int nt = 0; nt < 4; nt++)
                    mma_bf16(acc[mt][nt], ahi[mt], blo[nt]);
#pragma unroll
            for (int mt = 0; mt < 4; mt++)
#pragma unroll
                for (int nt = 0; nt < 4; nt++)
                    mma_bf16(acc[mt][nt], alo[mt], bhi[nt]);
        }
        __syncthreads();
    }

    // Epilogue: fragment layout (c0,c1)=(row=l/4, col=2*(l%4)+{0,1}),
    // (c2,c3)=row+8 same cols. Write float2 per pair.
    const int lrow = lane >> 2;
    const int lcol = (lane & 3) * 2;
#pragma unroll
    for (int mt = 0; mt < 4; mt++) {
#pragma unroll
        for (int nt = 0; nt < 4; nt++) {
            int row0 = by * 128 + wm * 64 + mt * 16 + lrow;
            int col  = bx * 128 + wn * 32 + nt * 8 + lcol;
#pragma unroll
            for (int half = 0; half < 2; half++) {
                int m = row0 + half * 8;
                float2 v = make_float2(acc[mt][nt][half * 2],
                                       acc[mt][nt][half * 2 + 1]);
                if (MODE == 0) {
                    *(float2*)&C0[(size_t)m * N + col] = v;
                } else {
                    int b = m >> 11, t = m & 2047, dd = col & 63;
                    if (col < 2048) {
                        int h = col >> 6;
                        *(float2*)&C0[((((size_t)b * NH_ + h) * QL_ + t) << 6) + dd] = v;
                    } else if (col < 2560) {
                        int h = (col - 2048) >> 6;
                        *(float2*)&C1[((((size_t)b * KVH_ + h) * QL_ + t) << 6) + dd] = v;
                    } else {
                        int h = (col - 2560) >> 6;
                        *(float2*)&C2[((((size_t)b * KVH_ + h) * QL_ + t) << 6) + dd] = v;
                    }
                }
            }
        }
    }
}

// ===========================================================================
// RoPE table (fp64 trig once — --use_fast_math breaks sincosf at ~2000 rad)
// ===========================================================================
__global__ void rope_table_kernel(float* __restrict__ ct, float* __restrict__ st,
                                  int Q)
{
    int idx = blockIdx.x * blockDim.x + threadIdx.x;
    if (idx >= Q * 32) return;
    int j = idx & 31;
    int t = idx >> 5;
    float freq = (float)(1.0 / pow(10000.0, (double)(2 * j) / 64.0));
    float ang  = (float)t * freq;
    double cd, sd;
    sincos((double)ang, &sd, &cd);
    ct[idx] = (float)cd;
    st[idx] = (float)sd;
}

__global__ void rope_apply_kernel(float* __restrict__ buf,
                                  const float* __restrict__ ct,
                                  const float* __restrict__ st,
                                  int Q, int total)
{
    int idx = blockIdx.x * blockDim.x + threadIdx.x;
    if (idx >= total) return;
    int j  = idx & 31;
    int t  = (idx >> 5) % Q;
    int bh = idx / (32 * Q);
    size_t base = ((size_t)bh * Q + t) * 64;

    float c = ct[(t << 5) + j];
    float s = st[(t << 5) + j];
    float x1 = buf[base + j];
    float x2 = buf[base + j + 32];
    buf[base + j]      = x1 * c - x2 * s;
    buf[base + j + 32] = x2 * c + x1 * s;
}

// ===========================================================================
// Causal flash attention with GQA (fp32). Output written as bf16 hi/lo split
// in [b*Q, H*64] row-major — ready as A operand for the Wo GEMM.
// ===========================================================================
#define QT_ST 132
#define KV_ST 68
#define ATTN_SMEM_FLOATS (64 * QT_ST + 64 * KV_ST + 64 * KV_ST + 128 * KV_ST)
#define ATTN_SMEM_BYTES  (ATTN_SMEM_FLOATS * 4)

__global__ void __launch_bounds__(256)
attn_kernel(const float* __restrict__ Qb, const float* __restrict__ Kb,
            const float* __restrict__ Vb,
            __nv_bfloat16* __restrict__ Ohi, __nv_bfloat16* __restrict__ Olo,
            int Q, int H, int KVH)
{
    extern __shared__ float smf[];
    float* Qt = smf;
    float* Kt = Qt + 64 * QT_ST;
    float* Vs = Kt + 64 * KV_ST;
    float* Ps = Vs + 64 * KV_ST;

    const int tid = threadIdx.x;
    const int tx  = tid & 15;
    const int ty  = tid >> 4;
    const int qt  = blockIdx.x;
    const int h   = blockIdx.y;
    const int b   = blockIdx.z;
    const int kvh = h / (H / KVH);
    const int q0  = qt * 128;

    const float* Qg = Qb + (((size_t)b * H + h) * Q + q0) * 64;
    const float* Kg = Kb + (((size_t)b * KVH + kvh) * Q) * 64;
    const float* Vg = Vb + (((size_t)b * KVH + kvh) * Q) * 64;

#pragma unroll
    for (int it = 0; it < 8; it++) {
        int f  = tid + it * 256;
        int r  = f >> 4;
        int d4 = f & 15;
        float4 v = *(const float4*)(Qg + (size_t)r * 64 + d4 * 4);
        Qt[(d4 * 4 + 0) * QT_ST + r] = v.x;
        Qt[(d4 * 4 + 1) * QT_ST + r] = v.y;
        Qt[(d4 * 4 + 2) * QT_ST + r] = v.z;
        Qt[(d4 * 4 + 3) * QT_ST + r] = v.w;
    }

    float m[8], l[8], acc[8][4];
#pragma unroll
    for (int i = 0; i < 8; i++) {
        m[i] = -1e30f;
        l[i] = 0.f;
#pragma unroll
        for (int j = 0; j < 4; j++) acc[i][j] = 0.f;
    }

    const int ktiles = (q0 + 128) / 64;
    const float scale = 0.125f;

    for (int kt = 0; kt < ktiles; kt++) {
        const int k0 = kt * 64;
        __syncthreads();

#pragma unroll
        for (int it = 0; it < 4; it++) {
            int f  = tid + it * 256;
            int c  = f >> 4;
            int d4 = f & 15;
            float4 kv = *(const float4*)(Kg + (size_t)(k0 + c) * 64 + d4 * 4);
            Kt[(d4 * 4 + 0) * KV_ST + c] = kv.x;
            Kt[(d4 * 4 + 1) * KV_ST + c] = kv.y;
            Kt[(d4 * 4 + 2) * KV_ST + c] = kv.z;
            Kt[(d4 * 4 + 3) * KV_ST + c] = kv.w;
            float4 vv = *(const float4*)(Vg + (size_t)(k0 + c) * 64 + d4 * 4);
            *(float4*)&Vs[c * KV_ST + d4 * 4] = vv;
        }
        __syncthreads();

        float s[8][4];
#pragma unroll
        for (int i = 0; i < 8; i++)
#pragma unroll
            for (int j = 0; j < 4; j++) s[i][j] = 0.f;

#pragma unroll 4
        for (int d = 0; d < 64; d++) {
            float4 q0v = *(float4*)&Qt[d * QT_ST + ty * 8];
            float4 q1v = *(float4*)&Qt[d * QT_ST + ty * 8 + 4];
            float4 kv  = *(float4*)&Kt[d * KV_ST + tx * 4];
            float qv[8] = {q0v.x, q0v.y, q0v.z, q0v.w, q1v.x, q1v.y, q1v.z, q1v.w};
            float kvv[4] = {kv.x, kv.y, kv.z, kv.w};
#pragma unroll
            for (int i = 0; i < 8; i++)
#pragma unroll
                for (int j = 0; j < 4; j++)
                    s[i][j] += qv[i] * kvv[j];
        }

#pragma unroll
        for (int i = 0; i < 8; i++) {
            int qg = q0 + ty * 8 + i;
            float rm = -1e30f;
#pragma unroll
            for (int j = 0; j < 4; j++) {
                int kg = k0 + tx * 4 + j;
                float v = s[i][j] * scale;
                if (kg > qg) v = -1e30f;
                s[i][j] = v;
                rm = fmaxf(rm, v);
            }
#pragma unroll
            for (int off = 8; off; off >>= 1)
                rm = fmaxf(rm, __shfl_xor_sync(0xffffffffu, rm, off));

            float newm = fmaxf(m[i], rm);
            float corr = __expf(m[i] - newm);
            float rsum = 0.f;
#pragma unroll
            for (int j = 0; j < 4; j++) {
                float p = __expf(s[i][j] - newm);
                s[i][j] = p;
                rsum += p;
            }
#pragma unroll
            for (int off = 8; off; off >>= 1)
                rsum += __shfl_xor_sync(0xffffffffu, rsum, off);

            l[i] = l[i] * corr + rsum;
            m[i] = newm;
#pragma unroll
            for (int j = 0; j < 4; j++) acc[i][j] *= corr;

            *(float4*)&Ps[(ty * 8 + i) * KV_ST + tx * 4] =
                make_float4(s[i][0], s[i][1], s[i][2], s[i][3]);
        }
        __syncthreads();

#pragma unroll 4
        for (int k = 0; k < 64; k++) {
            float4 vv = *(float4*)&Vs[k * KV_ST + tx * 4];
#pragma unroll
            for (int i = 0; i < 8; i++) {
                float p = Ps[(ty * 8 + i) * KV_ST + k];
                acc[i][0] += p * vv.x;
                acc[i][1] += p * vv.y;
                acc[i][2] += p * vv.z;
                acc[i][3] += p * vv.w;
            }
        }
    }

    const int HIDcols = H * 64;
#pragma unroll
    for (int i = 0; i < 8; i++) {
        float inv = 1.0f / l[i];
        int gr = b * Q + q0 + ty * 8 + i;
        int gc = h * 64 + tx * 4;
        size_t o = (size_t)gr * HIDcols + gc;
        float v0 = acc[i][0] * inv, v1 = acc[i][1] * inv;
        float v2 = acc[i][2] * inv, v3 = acc[i][3] * inv;
        __nv_bfloat16 h0 = __float2bfloat16(v0), h1 = __float2bfloat16(v1);
        __nv_bfloat16 h2 = __float2bfloat16(v2), h3 = __float2bfloat16(v3);
        *(__nv_bfloat162*)&Ohi[o]     = __halves2bfloat162(h0, h1);
        *(__nv_bfloat162*)&Ohi[o + 2] = __halves2bfloat162(h2, h3);
        __nv_bfloat16 l0 = __float2bfloat16(v0 - __bfloat162float(h0));
        __nv_bfloat16 l1 = __float2bfloat16(v1 - __bfloat162float(h1));
        __nv_bfloat16 l2 = __float2bfloat16(v2 - __bfloat162float(h2));
        __nv_bfloat16 l3 = __float2bfloat16(v3 - __bfloat162float(h3));
        *(__nv_bfloat162*)&Olo[o]     = __halves2bfloat162(l0, l1);
        *(__nv_bfloat162*)&Olo[o + 2] = __halves2bfloat162(l2, l3);
    }
}

// ===========================================================================
extern "C" void kernel_launch(void* const* d_in, const int* in_sizes, int n_in,
                              void* d_out, int out_size)
{
    const float* X  = (const float*)d_in[0];
    const float* Wq = (const float*)d_in[2];
    const float* Wk = (const float*)d_in[3];
    const float* Wv = (const float*)d_in[4];
    const float* Wo = (const float*)d_in[5];
    float* out = (float*)d_out;

    float *qp, *kp, *vp, *cp, *sp;
    __nv_bfloat16 *xhi, *xlo, *whi, *wlo, *ohi, *olo, *ahi, *alo;
    cudaGetSymbolAddress((void**)&qp, g_Q);
    cudaGetSymbolAddress((void**)&kp, g_K);
    cudaGetSymbolAddress((void**)&vp, g_V);
    cudaGetSymbolAddress((void**)&cp, g_cos);
    cudaGetSymbolAddress((void**)&sp, g_sin);
    cudaGetSymbolAddress((void**)&xhi, g_Xhi);
    cudaGetSymbolAddress((void**)&xlo, g_Xlo);
    cudaGetSymbolAddress((void**)&whi, g_Whi);
    cudaGetSymbolAddress((void**)&wlo, g_Wlo);
    cudaGetSymbolAddress((void**)&ohi, g_Ohi);
    cudaGetSymbolAddress((void**)&olo, g_Olo);
    cudaGetSymbolAddress((void**)&ahi, g_Ahi);
    cudaGetSymbolAddress((void**)&alo, g_Alo);

    const int M = B_ * QL_;   // 4096

    cudaFuncSetAttribute(mma_gemm<0>, cudaFuncAttributeMaxDynamicSharedMemorySize, MMA_SMEM_BYTES);
    cudaFuncSetAttribute(mma_gemm<1>, cudaFuncAttributeMaxDynamicSharedMemorySize, MMA_SMEM_BYTES);
    cudaFuncSetAttribute(attn_kernel, cudaFuncAttributeMaxDynamicSharedMemorySize, ATTN_SMEM_BYTES);

    // RoPE table + operand conversions
    rope_table_kernel<<<(QL_ * 32 + 255) / 256, 256>>>(cp, sp, QL_);
    split_kernel<<<(M * HID_ + 255) / 256, 256>>>(X, xhi, xlo, M * HID_);
    transpose_split_kernel<<<dim3(2048 / 32, HID_ / 32), dim3(32, 8)>>>(Wq, whi, wlo, HID_, 2048, 0);
    transpose_split_kernel<<<dim3(512 / 32,  HID_ / 32), dim3(32, 8)>>>(Wk, whi, wlo, HID_, 512, 2048);
    transpose_split_kernel<<<dim3(512 / 32,  HID_ / 32), dim3(32, 8)>>>(Wv, whi, wlo, HID_, 512, 2560);
    transpose_split_kernel<<<dim3(2048 / 32, HID_ / 32), dim3(32, 8)>>>(Wo, ohi, olo, HID_, 2048, 0);

    // Fused QKV projection on tensor cores (scatter to head layouts)
    mma_gemm<1><<<dim3(3072 / 128, M / 128), 256, MMA_SMEM_BYTES>>>(
        xhi, xlo, whi, wlo, qp, kp, vp, M, 3072, HID_);

    // RoPE on Q and K
    {
        int totq = B_ * NH_  * QL_ * 32;
        int totk = B_ * KVH_ * QL_ * 32;
        rope_apply_kernel<<<(totq + 255) / 256, 256>>>(qp, cp, sp, QL_, totq);
        rope_apply_kernel<<<(totk + 255) / 256, 256>>>(kp, cp, sp, QL_, totk);
    }

    // Attention (fp32), emits bf16 hi/lo split output
    attn_kernel<<<dim3(QL_ / 128, NH_, B_), 256, ATTN_SMEM_BYTES>>>(
        qp, kp, vp, ahi, alo, QL_, NH_, KVH_);

    // Output projection on tensor cores
    mma_gemm<0><<<dim3(HID_ / 128, M / 128), 256, MMA_SMEM_BYTES>>>(
        ahi, alo, ohi, olo, out, nullptr, nullptr, M, HID_, HID_);
}

// round 10
// speedup vs baseline: 2.4031x; 1.5766x over previous
#include <cuda_runtime.h>
#include <cuda_bf16.h>
#include <math.h>
#include <stdint.h>

// Problem constants
#define B_   2
#define QL_  2048
#define HID_ 2048
#define NH_  32
#define KVH_ 8
#define D_   64

// ===========================================================================
// PTX helpers — BASE PTX ONLY (harness targets plain sm_103: no tcgen05!)
// ===========================================================================
__device__ __forceinline__ uint32_t smem_u32(const void* p) {
    uint32_t a;
    asm("{ .reg .u64 t; cvta.to.shared.u64 t, %1; cvt.u32.u64 %0, t; }"
        : "=r"(a) : "l"(p));
    return a;
}
__device__ __forceinline__ void ldmat_x4(uint32_t* r, uint32_t addr) {
    asm volatile("ldmatrix.sync.aligned.m8n8.x4.shared.b16 {%0,%1,%2,%3}, [%4];"
                 : "=r"(r[0]), "=r"(r[1]), "=r"(r[2]), "=r"(r[3]) : "r"(addr));
}
__device__ __forceinline__ void ldmat_x2(uint32_t* r, uint32_t addr) {
    asm volatile("ldmatrix.sync.aligned.m8n8.x2.shared.b16 {%0,%1}, [%2];"
                 : "=r"(r[0]), "=r"(r[1]) : "r"(addr));
}
__device__ __forceinline__ void mma_bf16(float* d, const uint32_t* a, const uint32_t* b) {
    asm volatile("mma.sync.aligned.m16n8k16.row.col.f32.bf16.bf16.f32 "
                 "{%0,%1,%2,%3}, {%4,%5,%6,%7}, {%8,%9}, {%0,%1,%2,%3};"
                 : "+f"(d[0]), "+f"(d[1]), "+f"(d[2]), "+f"(d[3])
                 : "r"(a[0]), "r"(a[1]), "r"(a[2]), "r"(a[3]),
                   "r"(b[0]), "r"(b[1]));
}
__device__ __forceinline__ void cp_async16(uint32_t dst, const void* src) {
    asm volatile("cp.async.cg.shared.global [%0], [%1], 16;"
                 :: "r"(dst), "l"(src));
}
#define CP_COMMIT()  asm volatile("cp.async.commit_group;" ::: "memory")
#define CP_WAIT(n)   asm volatile("cp.async.wait_group %0;" :: "n"(n) : "memory")

// ===========================================================================
// Scratch (device globals — no allocation allowed)
// ===========================================================================
__device__ float g_Q[(size_t)B_ * NH_  * QL_ * D_];   // [b,h,q,d] fp32
__device__ float g_K[(size_t)B_ * KVH_ * QL_ * D_];
__device__ float g_V[(size_t)B_ * KVH_ * QL_ * D_];
__device__ float g_cos[QL_ * 32];
__device__ float g_sin[QL_ * 32];
// bf16 split operands
__device__ __nv_bfloat16 g_Xhi[(size_t)B_ * QL_ * HID_];
__device__ __nv_bfloat16 g_Xlo[(size_t)B_ * QL_ * HID_];
__device__ __nv_bfloat16 g_Whi[(size_t)3072 * HID_];
__device__ __nv_bfloat16 g_Wlo[(size_t)3072 * HID_];
__device__ __nv_bfloat16 g_Ohi[(size_t)HID_ * HID_];
__device__ __nv_bfloat16 g_Olo[(size_t)HID_ * HID_];
__device__ __nv_bfloat16 g_Ahi[(size_t)B_ * QL_ * HID_];
__device__ __nv_bfloat16 g_Alo[(size_t)B_ * QL_ * HID_];
// bf16 attention operands
__device__ __nv_bfloat16 g_Qbh[(size_t)B_ * NH_  * QL_ * D_];  // roped Q hi/lo
__device__ __nv_bfloat16 g_Qbl[(size_t)B_ * NH_  * QL_ * D_];
__device__ __nv_bfloat16 g_Kbh[(size_t)B_ * KVH_ * QL_ * D_];
__device__ __nv_bfloat16 g_Kbl[(size_t)B_ * KVH_ * QL_ * D_];
__device__ __nv_bfloat16 g_Vth[(size_t)B_ * KVH_ * D_ * QL_]; // V^T [b,kvh,d,seq]
__device__ __nv_bfloat16 g_Vtl[(size_t)B_ * KVH_ * D_ * QL_];

// ===========================================================================
// fp32 -> (bf16 hi, bf16 lo) split
// ===========================================================================
__global__ void split_kernel(const float* __restrict__ src,
                             __nv_bfloat16* __restrict__ hi,
                             __nv_bfloat16* __restrict__ lo, int n)
{
    int i = blockIdx.x * blockDim.x + threadIdx.x;
    if (i >= n) return;
    float v = src[i];
    __nv_bfloat16 h = __float2bfloat16(v);
    hi[i] = h;
    lo[i] = __float2bfloat16(v - __bfloat162float(h));
}

// Transpose + split: W[K, Ncols] -> T[(rowOffset+n), k] bf16 hi/lo, ldT = K.
__global__ void transpose_split_kernel(const float* __restrict__ W,
                                       __nv_bfloat16* __restrict__ Thi,
                                       __nv_bfloat16* __restrict__ Tlo,
                                       int K, int Ncols, int rowOffset)
{
    __shared__ float tile[32][33];
    int k0 = blockIdx.y * 32, n0 = blockIdx.x * 32;
    int tx = threadIdx.x, ty = threadIdx.y;
#pragma unroll
    for (int i = 0; i < 4; i++) {
        int k = k0 + ty + i * 8;
        tile[ty + i * 8][tx] = W[(size_t)k * Ncols + n0 + tx];
    }
    __syncthreads();
#pragma unroll
    for (int i = 0; i < 4; i++) {
        int n = n0 + ty + i * 8;
        float v = tile[tx][ty + i * 8];
        __nv_bfloat16 h = __float2bfloat16(v);
        size_t o = (size_t)(rowOffset + n) * K + k0 + tx;
        Thi[o] = h;
        Tlo[o] = __float2bfloat16(v - __bfloat162float(h));
    }
}

// V transpose+split: g_V [bk, seq, 64] fp32 -> Vt [bk, 64, 2048] bf16 hi/lo
__global__ void vtrans_split_kernel(const float* __restrict__ V,
                                    __nv_bfloat16* __restrict__ Thi,
                                    __nv_bfloat16* __restrict__ Tlo)
{
    __shared__ float tile[32][33];
    int bk = blockIdx.z;
    int s0 = blockIdx.x * 32, d0 = blockIdx.y * 32;
    int tx = threadIdx.x, ty = threadIdx.y;
    const float* Vb = V + (size_t)bk * QL_ * 64;
#pragma unroll
    for (int i = 0; i < 4; i++) {
        int s = s0 + ty + i * 8;
        tile[ty + i * 8][tx] = Vb[(size_t)s * 64 + d0 + tx];
    }
    __syncthreads();
#pragma unroll
    for (int i = 0; i < 4; i++) {
        int d = d0 + ty + i * 8;
        float v = tile[tx][ty + i * 8];   // element (s=s0+tx, d)
        __nv_bfloat16 h = __float2bfloat16(v);
        size_t o = (size_t)bk * 64 * QL_ + (size_t)d * QL_ + s0 + tx;
        Thi[o] = h;
        Tlo[o] = __float2bfloat16(v - __bfloat162float(h));
    }
}

// ===========================================================================
// mma.sync bf16x3 GEMM (unchanged from passing R9)
// ===========================================================================
#define TILE_B   18432
#define STAGE_B  (4 * TILE_B)
#define MMA_SMEM_BYTES (2 * STAGE_B)

template<int MODE>
__global__ void __launch_bounds__(256)
mma_gemm(const __nv_bfloat16* __restrict__ Ahi, const __nv_bfloat16* __restrict__ Alo,
         const __nv_bfloat16* __restrict__ Bhi, const __nv_bfloat16* __restrict__ Blo,
         float* __restrict__ C0, float* __restrict__ C1, float* __restrict__ C2,
         int M, int N, int K)
{
    extern __shared__ char smc[];
    const uint32_t sbase = smem_u32(smc);
    const int tid  = threadIdx.x;
    const int wid  = tid >> 5;
    const int lane = tid & 31;
    const int bx   = blockIdx.x;
    const int by   = blockIdx.y;
    const int wm   = wid >> 2;
    const int wn   = wid & 3;

    float acc[4][4][4];
#pragma unroll
    for (int mt = 0; mt < 4; mt++)
#pragma unroll
        for (int nt = 0; nt < 4; nt++)
#pragma unroll
            for (int r = 0; r < 4; r++) acc[mt][nt][r] = 0.f;

    const int NC = K >> 6;

    auto load_chunk = [&](int ci, int s) {
        const int k0 = ci * 64;
        const uint32_t sb = sbase + s * STAGE_B;
#pragma unroll
        for (int it = 0; it < 4; it++) {
            int f = tid + it * 256;
            int r = f >> 3, seg = f & 7;
            uint32_t dst = sb + r * 144 + seg * 16;
            size_t ga = (size_t)(by * 128 + r) * K + k0 + seg * 8;
            size_t gb = (size_t)(bx * 128 + r) * K + k0 + seg * 8;
            cp_async16(dst,              Ahi + ga);
            cp_async16(dst + TILE_B,     Alo + ga);
            cp_async16(dst + 2 * TILE_B, Bhi + gb);
            cp_async16(dst + 3 * TILE_B, Blo + gb);
        }
        CP_COMMIT();
    };

    load_chunk(0, 0);

    for (int ci = 0; ci < NC; ci++) {
        const int s = ci & 1;
        if (ci + 1 < NC) { load_chunk(ci + 1, s ^ 1); CP_WAIT(1); }
        else             { CP_WAIT(0); }
        __syncthreads();

        const uint32_t sb    = sbase + s * STAGE_B;
        const uint32_t aBase = sb + wm * 64 * 144;
        const uint32_t bBase = sb + 2 * TILE_B + wn * 32 * 144;

        const int ar = lane & 15;
        const int acol = (lane >> 4) * 8;
        const int br = lane & 7;
        const int bcol = ((lane >> 3) & 1) * 8;

#pragma unroll
        for (int ks = 0; ks < 4; ks++) {
            const int kc = ks * 16;
            uint32_t ahi[4][4], alo[4][4], bhi[4][2], blo[4][2];
#pragma unroll
            for (int mt = 0; mt < 4; mt++) {
                uint32_t a = aBase + (mt * 16 + ar) * 144 + (kc + acol) * 2;
                ldmat_x4(ahi[mt], a);
                ldmat_x4(alo[mt], a + TILE_B);
            }
#pragma unroll
            for (int nt = 0; nt < 4; nt++) {
                uint32_t b = bBase + (nt * 8 + br) * 144 + (kc + bcol) * 2;
                ldmat_x2(bhi[nt], b);
                ldmat_x2(blo[nt], b + TILE_B);
            }
#pragma unroll
            for (int mt = 0; mt < 4; mt++)
#pragma unroll
                for (int nt = 0; nt < 4; nt++)
                    mma_bf16(acc[mt][nt], ahi[mt], bhi[nt]);
#pragma unroll
            for (int mt = 0; mt < 4; mt++)
#pragma unroll
                for (int nt = 0; nt < 4; nt++)
                    mma_bf16(acc[mt][nt], ahi[mt], blo[nt]);
#pragma unroll
            for (int mt = 0; mt < 4; mt++)
#pragma unroll
                for (int nt = 0; nt < 4; nt++)
                    mma_bf16(acc[mt][nt], alo[mt], bhi[nt]);
        }
        __syncthreads();
    }

    const int lrow = lane >> 2;
    const int lcol = (lane & 3) * 2;
#pragma unroll
    for (int mt = 0; mt < 4; mt++) {
#pragma unroll
        for (int nt = 0; nt < 4; nt++) {
            int row0 = by * 128 + wm * 64 + mt * 16 + lrow;
            int col  = bx * 128 + wn * 32 + nt * 8 + lcol;
#pragma unroll
            for (int half = 0; half < 2; half++) {
                int m = row0 + half * 8;
                float2 v = make_float2(acc[mt][nt][half * 2],
                                       acc[mt][nt][half * 2 + 1]);
                if (MODE == 0) {
                    *(float2*)&C0[(size_t)m * N + col] = v;
                } else {
                    int b = m >> 11, t = m & 2047, dd = col & 63;
                    if (col < 2048) {
                        int h = col >> 6;
                        *(float2*)&C0[((((size_t)b * NH_ + h) * QL_ + t) << 6) + dd] = v;
                    } else if (col < 2560) {
                        int h = (col - 2048) >> 6;
                        *(float2*)&C1[((((size_t)b * KVH_ + h) * QL_ + t) << 6) + dd] = v;
                    } else {
                        int h = (col - 2560) >> 6;
                        *(float2*)&C2[((((size_t)b * KVH_ + h) * QL_ + t) << 6) + dd] = v;
                    }
                }
            }
        }
    }
}

// ===========================================================================
// RoPE
// ===========================================================================
__global__ void rope_table_kernel(float* __restrict__ ct, float* __restrict__ st,
                                  int Q)
{
    int idx = blockIdx.x * blockDim.x + threadIdx.x;
    if (idx >= Q * 32) return;
    int j = idx & 31;
    int t = idx >> 5;
    float freq = (float)(1.0 / pow(10000.0, (double)(2 * j) / 64.0));
    float ang  = (float)t * freq;
    double cd, sd;
    sincos((double)ang, &sd, &cd);
    ct[idx] = (float)cd;
    st[idx] = (float)sd;
}

// RoPE apply: reads fp32, writes bf16 hi/lo (attention operand format)
__global__ void rope_apply_bf16(const float* __restrict__ buf,
                                const float* __restrict__ ct,
                                const float* __restrict__ st,
                                __nv_bfloat16* __restrict__ oh,
                                __nv_bfloat16* __restrict__ ol,
                                int Q, int total)
{
    int idx = blockIdx.x * blockDim.x + threadIdx.x;
    if (idx >= total) return;
    int j  = idx & 31;
    int t  = (idx >> 5) % Q;
    int bh = idx / (32 * Q);
    size_t base = ((size_t)bh * Q + t) * 64;

    float c = ct[(t << 5) + j];
    float s = st[(t << 5) + j];
    float x1 = buf[base + j];
    float x2 = buf[base + j + 32];
    float r1 = x1 * c - x2 * s;
    float r2 = x2 * c + x1 * s;
    __nv_bfloat16 h1 = __float2bfloat16(r1);
    __nv_bfloat16 h2 = __float2bfloat16(r2);
    oh[base + j]      = h1;
    oh[base + j + 32] = h2;
    ol[base + j]      = __float2bfloat16(r1 - __bfloat162float(h1));
    ol[base + j + 32] = __float2bfloat16(r2 - __bfloat162float(h2));
}

// ===========================================================================
// Flash attention on mma.sync bf16x3. Grid (QL/128, NH, B), 256 thr, 8 warps.
// Warp w owns q rows [w*16, w*16+16). BK=64 per kv tile, double-buffered.
// SMEM: 2 stages x {Khi,Klo,Vthi,Vtlo}[64][72bf16] + Q hi/lo [128][72bf16].
// ===========================================================================
#define AT_KTILE 9216                  // 64 rows * 144 B
#define AT_STAGE (4 * AT_KTILE)        // 36864
#define AT_Q_OFF (2 * AT_STAGE)        // 73728
#define AT_SMEM  (AT_Q_OFF + 2 * 128 * 144)   // 110592

__global__ void __launch_bounds__(256, 1)
attn_mma(const __nv_bfloat16* __restrict__ Qh, const __nv_bfloat16* __restrict__ Ql,
         const __nv_bfloat16* __restrict__ Kh, const __nv_bfloat16* __restrict__ Kl,
         const __nv_bfloat16* __restrict__ Vth, const __nv_bfloat16* __restrict__ Vtl,
         __nv_bfloat16* __restrict__ Ohi, __nv_bfloat16* __restrict__ Olo)
{
    extern __shared__ char smc[];
    const uint32_t sbase = smem_u32(smc);
    const int tid  = threadIdx.x;
    const int wid  = tid >> 5;
    const int lane = tid & 31;
    const int qt   = blockIdx.x;
    const int h    = blockIdx.y;
    const int b    = blockIdx.z;
    const int kvh  = h >> 2;           // NH/KVH = 4
    const int q0   = qt * 128;

    const __nv_bfloat16* Qgh = Qh + (((size_t)b * NH_ + h) * QL_ + q0) * 64;
    const __nv_bfloat16* Qgl = Ql + (((size_t)b * NH_ + h) * QL_ + q0) * 64;
    const __nv_bfloat16* Kgh = Kh + (((size_t)b * KVH_ + kvh) * QL_) * 64;
    const __nv_bfloat16* Kgl = Kl + (((size_t)b * KVH_ + kvh) * QL_) * 64;
    const __nv_bfloat16* Vgh = Vth + (((size_t)b * KVH_ + kvh) * 64) * QL_;
    const __nv_bfloat16* Vgl = Vtl + (((size_t)b * KVH_ + kvh) * 64) * QL_;

    // ---- issue Q loads (group 0) ----
#pragma unroll
    for (int it = 0; it < 4; it++) {
        int f = tid + it * 256;        // 0..1023
        int r = f >> 3, seg = f & 7;
        uint32_t dst = sbase + AT_Q_OFF + r * 144 + seg * 16;
        cp_async16(dst,               Qgh + (size_t)r * 64 + seg * 8);
        cp_async16(dst + 128 * 144,   Qgl + (size_t)r * 64 + seg * 8);
    }
    CP_COMMIT();

    auto load_kv = [&](int kt, int s) {
        const int k0 = kt * 64;
        const uint32_t sb = sbase + s * AT_STAGE;
#pragma unroll
        for (int it = 0; it < 2; it++) {
            int f = tid + it * 256;    // 0..511
            int r = f >> 3, seg = f & 7;
            uint32_t dst = sb + r * 144 + seg * 16;
            size_t gk = (size_t)(k0 + r) * 64 + seg * 8;
            size_t gv = (size_t)r * QL_ + k0 + seg * 8;
            cp_async16(dst,                Kgh + gk);
            cp_async16(dst + AT_KTILE,     Kgl + gk);
            cp_async16(dst + 2 * AT_KTILE, Vgh + gv);
            cp_async16(dst + 3 * AT_KTILE, Vgl + gv);
        }
        CP_COMMIT();
    };

    load_kv(0, 0);

    // ---- wait Q, preload Q fragments into registers ----
    CP_WAIT(1);
    __syncthreads();

    const int ar   = lane & 15;
    const int acol = (lane >> 4) * 8;
    const int br   = lane & 7;
    const int bcol = ((lane >> 3) & 1) * 8;

    uint32_t qfh[4][4], qfl[4][4];
    {
        uint32_t qBase = sbase + AT_Q_OFF + (wid * 16 + ar) * 144;
#pragma unroll
        for (int ks = 0; ks < 4; ks++) {
            uint32_t a = qBase + (ks * 16 + acol) * 2;
            ldmat_x4(qfh[ks], a);
            ldmat_x4(qfl[ks], a + 128 * 144);
        }
    }

    float o[8][4];
#pragma unroll
    for (int nt = 0; nt < 8; nt++)
#pragma unroll
        for (int j = 0; j < 4; j++) o[nt][j] = 0.f;
    float m0 = -1e30f, m1 = -1e30f, l0 = 0.f, l1 = 0.f;

    const int ktiles = qt * 2 + 2;
    const int qg0 = q0 + wid * 16 + (lane >> 2);
    const int qg1 = qg0 + 8;
    const int lc2 = (lane & 3) * 2;

    for (int kt = 0; kt < ktiles; kt++) {
        const int s = kt & 1;
        if (kt + 1 < ktiles) { load_kv(kt + 1, s ^ 1); CP_WAIT(1); }
        else                 { CP_WAIT(0); }
        __syncthreads();

        const uint32_t kb = sbase + s * AT_STAGE;
        const uint32_t vb = kb + 2 * AT_KTILE;
        const int k0 = kt * 64;

        // ---- S = Q K^T (bf16x3) ----
        float sf[8][4];
#pragma unroll
        for (int nt = 0; nt < 8; nt++)
#pragma unroll
            for (int j = 0; j < 4; j++) sf[nt][j] = 0.f;

#pragma unroll
        for (int ks = 0; ks < 4; ks++) {
            uint32_t bh[8][2], bl[8][2];
#pragma unroll
            for (int nt = 0; nt < 8; nt++) {
                uint32_t a = kb + (nt * 8 + br) * 144 + (ks * 16 + bcol) * 2;
                ldmat_x2(bh[nt], a);
                ldmat_x2(bl[nt], a + AT_KTILE);
            }
#pragma unroll
            for (int nt = 0; nt < 8; nt++) mma_bf16(sf[nt], qfh[ks], bh[nt]);
#pragma unroll
            for (int nt = 0; nt < 8; nt++) mma_bf16(sf[nt], qfh[ks], bl[nt]);
#pragma unroll
            for (int nt = 0; nt < 8; nt++) mma_bf16(sf[nt], qfl[ks], bh[nt]);
        }

        // ---- scale + causal mask + row max ----
        const bool domask = (kt >= ktiles - 2);
        float rm0 = -1e30f, rm1 = -1e30f;
#pragma unroll
        for (int nt = 0; nt < 8; nt++) {
            int kg = k0 + nt * 8 + lc2;
#pragma unroll
            for (int j = 0; j < 4; j++) {
                float v = sf[nt][j] * 0.125f;
                if (domask) {
                    int kcol = kg + (j & 1);
                    int qrow = (j < 2) ? qg0 : qg1;
                    if (kcol > qrow) v = -1e30f;
                }
                sf[nt][j] = v;
                if (j < 2) rm0 = fmaxf(rm0, v); else rm1 = fmaxf(rm1, v);
            }
        }
        rm0 = fmaxf(rm0, __shfl_xor_sync(0xffffffffu, rm0, 1));
        rm0 = fmaxf(rm0, __shfl_xor_sync(0xffffffffu, rm0, 2));
        rm1 = fmaxf(rm1, __shfl_xor_sync(0xffffffffu, rm1, 1));
        rm1 = fmaxf(rm1, __shfl_xor_sync(0xffffffffu, rm1, 2));

        float nm0 = fmaxf(m0, rm0), nm1 = fmaxf(m1, rm1);
        float c0 = __expf(m0 - nm0), c1 = __expf(m1 - nm1);

        // ---- exp + row sum + pack P to bf16 hi/lo A-fragments ----
        float rs0 = 0.f, rs1 = 0.f;
        uint32_t ph[8][2], pl[8][2];
#pragma unroll
        for (int nt = 0; nt < 8; nt++) {
            float p0 = __expf(sf[nt][0] - nm0);
            float p1 = __expf(sf[nt][1] - nm0);
            float p2 = __expf(sf[nt][2] - nm1);
            float p3 = __expf(sf[nt][3] - nm1);
            rs0 += p0 + p1;
            rs1 += p2 + p3;
            __nv_bfloat162 h01 = __floats2bfloat162_rn(p0, p1);
            __nv_bfloat162 h23 = __floats2bfloat162_rn(p2, p3);
            ph[nt][0] = *(uint32_t*)&h01;
            ph[nt][1] = *(uint32_t*)&h23;
            __nv_bfloat162 l01 = __floats2bfloat162_rn(
                p0 - __bfloat162float(h01.x), p1 - __bfloat162float(h01.y));
            __nv_bfloat162 l23 = __floats2bfloat162_rn(
                p2 - __bfloat162float(h23.x), p3 - __bfloat162float(h23.y));
            pl[nt][0] = *(uint32_t*)&l01;
            pl[nt][1] = *(uint32_t*)&l23;
        }
        rs0 += __shfl_xor_sync(0xffffffffu, rs0, 1);
        rs0 += __shfl_xor_sync(0xffffffffu, rs0, 2);
        rs1 += __shfl_xor_sync(0xffffffffu, rs1, 1);
        rs1 += __shfl_xor_sync(0xffffffffu, rs1, 2);

        l0 = l0 * c0 + rs0;
        l1 = l1 * c1 + rs1;
        m0 = nm0;
        m1 = nm1;

        // rescale O
#pragma unroll
        for (int nt = 0; nt < 8; nt++) {
            o[nt][0] *= c0; o[nt][1] *= c0;
            o[nt][2] *= c1; o[nt][3] *= c1;
        }

        // ---- O += P V  (bf16x3: PhVh + PlVh + PhVl) ----
#pragma unroll
        for (int ks = 0; ks < 4; ks++) {
            uint32_t bh[8][2], bl[8][2];
#pragma unroll
            for (int nt = 0; nt < 8; nt++) {
                uint32_t a = vb + (nt * 8 + br) * 144 + (ks * 16 + bcol) * 2;
                ldmat_x2(bh[nt], a);
                ldmat_x2(bl[nt], a + AT_KTILE);
            }
            uint32_t pah[4] = {ph[2 * ks][0], ph[2 * ks][1],
                               ph[2 * ks + 1][0], ph[2 * ks + 1][1]};
            uint32_t pal[4] = {pl[2 * ks][0], pl[2 * ks][1],
                               pl[2 * ks + 1][0], pl[2 * ks + 1][1]};
#pragma unroll
            for (int nt = 0; nt < 8; nt++) mma_bf16(o[nt], pah, bh[nt]);
#pragma unroll
            for (int nt = 0; nt < 8; nt++) mma_bf16(o[nt], pal, bh[nt]);
#pragma unroll
            for (int nt = 0; nt < 8; nt++) mma_bf16(o[nt], pah, bl[nt]);
        }
        __syncthreads();
    }

    // ---- epilogue: O/l -> bf16 hi/lo split, [b*Q + q, h*64 + d] ----
    float inv0 = 1.0f / l0, inv1 = 1.0f / l1;
    int gr0 = b * QL_ + q0 + wid * 16 + (lane >> 2);
    int gr1 = gr0 + 8;
#pragma unroll
    for (int nt = 0; nt < 8; nt++) {
        int gc = h * 64 + nt * 8 + lc2;
        float v0 = o[nt][0] * inv0, v1 = o[nt][1] * inv0;
        float v2 = o[nt][2] * inv1, v3 = o[nt][3] * inv1;
        __nv_bfloat162 h01 = __floats2bfloat162_rn(v0, v1);
        __nv_bfloat162 h23 = __floats2bfloat162_rn(v2, v3);
        size_t o0 = (size_t)gr0 * HID_ + gc;
        size_t o1 = (size_t)gr1 * HID_ + gc;
        *(__nv_bfloat162*)&Ohi[o0] = h01;
        *(__nv_bfloat162*)&Ohi[o1] = h23;
        __nv_bfloat162 l01 = __floats2bfloat162_rn(
            v0 - __bfloat162float(h01.x), v1 - __bfloat162float(h01.y));
        __nv_bfloat162 l23 = __floats2bfloat162_rn(
            v2 - __bfloat162float(h23.x), v3 - __bfloat162float(h23.y));
        *(__nv_bfloat162*)&Olo[o0] = l01;
        *(__nv_bfloat162*)&Olo[o1] = l23;
    }
}

// ===========================================================================
extern "C" void kernel_launch(void* const* d_in, const int* in_sizes, int n_in,
                              void* d_out, int out_size)
{
    const float* X  = (const float*)d_in[0];
    const float* Wq = (const float*)d_in[2];
    const float* Wk = (const float*)d_in[3];
    const float* Wv = (const float*)d_in[4];
    const float* Wo = (const float*)d_in[5];
    float* out = (float*)d_out;

    float *qp, *kp, *vp, *cp, *sp;
    __nv_bfloat16 *xhi, *xlo, *whi, *wlo, *ohi, *olo, *ahi, *alo;
    __nv_bfloat16 *qbh, *qbl, *kbh, *kbl, *vth, *vtl;
    cudaGetSymbolAddress((void**)&qp, g_Q);
    cudaGetSymbolAddress((void**)&kp, g_K);
    cudaGetSymbolAddress((void**)&vp, g_V);
    cudaGetSymbolAddress((void**)&cp, g_cos);
    cudaGetSymbolAddress((void**)&sp, g_sin);
    cudaGetSymbolAddress((void**)&xhi, g_Xhi);
    cudaGetSymbolAddress((void**)&xlo, g_Xlo);
    cudaGetSymbolAddress((void**)&whi, g_Whi);
    cudaGetSymbolAddress((void**)&wlo, g_Wlo);
    cudaGetSymbolAddress((void**)&ohi, g_Ohi);
    cudaGetSymbolAddress((void**)&olo, g_Olo);
    cudaGetSymbolAddress((void**)&ahi, g_Ahi);
    cudaGetSymbolAddress((void**)&alo, g_Alo);
    cudaGetSymbolAddress((void**)&qbh, g_Qbh);
    cudaGetSymbolAddress((void**)&qbl, g_Qbl);
    cudaGetSymbolAddress((void**)&kbh, g_Kbh);
    cudaGetSymbolAddress((void**)&kbl, g_Kbl);
    cudaGetSymbolAddress((void**)&vth, g_Vth);
    cudaGetSymbolAddress((void**)&vtl, g_Vtl);

    const int M = B_ * QL_;   // 4096

    cudaFuncSetAttribute(mma_gemm<0>, cudaFuncAttributeMaxDynamicSharedMemorySize, MMA_SMEM_BYTES);
    cudaFuncSetAttribute(mma_gemm<1>, cudaFuncAttributeMaxDynamicSharedMemorySize, MMA_SMEM_BYTES);
    cudaFuncSetAttribute(attn_mma, cudaFuncAttributeMaxDynamicSharedMemorySize, AT_SMEM);

    // RoPE table + operand conversions
    rope_table_kernel<<<(QL_ * 32 + 255) / 256, 256>>>(cp, sp, QL_);
    split_kernel<<<(M * HID_ + 255) / 256, 256>>>(X, xhi, xlo, M * HID_);
    transpose_split_kernel<<<dim3(2048 / 32, HID_ / 32), dim3(32, 8)>>>(Wq, whi, wlo, HID_, 2048, 0);
    transpose_split_kernel<<<dim3(512 / 32,  HID_ / 32), dim3(32, 8)>>>(Wk, whi, wlo, HID_, 512, 2048);
    transpose_split_kernel<<<dim3(512 / 32,  HID_ / 32), dim3(32, 8)>>>(Wv, whi, wlo, HID_, 512, 2560);
    transpose_split_kernel<<<dim3(2048 / 32, HID_ / 32), dim3(32, 8)>>>(Wo, ohi, olo, HID_, 2048, 0);

    // Fused QKV projection on tensor cores (scatter to head layouts, fp32)
    mma_gemm<1><<<dim3(3072 / 128, M / 128), 256, MMA_SMEM_BYTES>>>(
        xhi, xlo, whi, wlo, qp, kp, vp, M, 3072, HID_);

    // RoPE -> bf16 hi/lo Q,K ; V^T split
    {
        int totq = B_ * NH_  * QL_ * 32;
        int totk = B_ * KVH_ * QL_ * 32;
        rope_apply_bf16<<<(totq + 255) / 256, 256>>>(qp, cp, sp, qbh, qbl, QL_, totq);
        rope_apply_bf16<<<(totk + 255) / 256, 256>>>(kp, cp, sp, kbh, kbl, QL_, totk);
        vtrans_split_kernel<<<dim3(QL_ / 32, 2, B_ * KVH_), dim3(32, 8)>>>(vp, vth, vtl);
    }

    // Attention on tensor cores, emits bf16 hi/lo split output
    attn_mma<<<dim3(QL_ / 128, NH_, B_), 256, AT_SMEM>>>(
        qbh, qbl, kbh, kbl, vth, vtl, ahi, alo);

    // Output projection on tensor cores
    mma_gemm<0><<<dim3(HID_ / 128, M / 128), 256, MMA_SMEM_BYTES>>>(
        ahi, alo, ohi, olo, out, nullptr, nullptr, M, HID_, HID_);
}